// round 13
// baseline (speedup 1.0000x reference)
#include <cuda_runtime.h>
#include <cstdint>

// ---------------------------------------------------------------------------
// FeaStEncoderBlock, input-space aggregation + bf16-split tensor-core GEMM.
// Round 13 (CSR-path restructure):
//   - k_scan: 10 values/thread preloaded (2 latency-exposed rounds, was 5)
//   - k_init eliminated: g_deg reset by k_fill, g_cur reset by k_agg_in
//     (deferred-reset; __device__ globals start zeroed, each run re-zeroes)
//   - edge passthrough fused into k_hist (single read of edge_index)
// GEMM unchanged (HMMA roofline). agg unchanged (near L2-BW bound).
// ---------------------------------------------------------------------------

#define MAXN 20000
#define MAXE 320000

__device__ __align__(16) uint32_t g_yh[(size_t)MAXN * 512];   // z hi pair-words
__device__ __align__(16) uint32_t g_yl[(size_t)MAXN * 512];   // z lo pair-words
__device__ __align__(16) float    g_h[(size_t)MAXN * 256];    // hidden h
__device__ __align__(16) uint32_t g_wbh0[320 * 256];          // conv0 W hi
__device__ __align__(16) uint32_t g_wbl0[320 * 256];          // conv0 W lo
__device__ __align__(16) uint32_t g_wbh1[512 * 256];          // conv1 W hi
__device__ __align__(16) uint32_t g_wbl1[512 * 256];          // conv1 W lo
__device__ __align__(16) float    g_ea[MAXN * 4];
__device__ __align__(16) float    g_eb[MAXN * 4];
__device__ int g_deg[MAXN];        // zeroed at load; re-zeroed by k_fill
__device__ int g_cur[MAXN];        // zeroed at load; re-zeroed by k_agg_in
__device__ int g_offs[MAXN + 1];
__device__ int g_srcs[MAXN + MAXE];

// ------------------------------- histogram + edge passthrough (fused, 1 read)
__global__ void k_hist_edges(const int* __restrict__ ei,
                             float* __restrict__ out,
                             int E, int n, int do_edges) {
    int t = blockIdx.x * blockDim.x + threadIdx.x;
    if (t >= E) return;
    int s = ei[t], d = ei[E + t];
    if (do_edges) {
        out[t]     = (float)s;
        out[E + t] = (float)d;
    }
    if (d >= 0 && d < n) atomicAdd(&g_deg[d], 1);
}

// single-block exclusive scan; 10 preloaded values/thread (self-loop +1 folded)
__global__ void k_scan(int n) {
    __shared__ int wsum[32];
    __shared__ int carry;
    const int VPT = 10;
    const int CH  = 1024 * VPT;
    int tid = threadIdx.x, lane = tid & 31, w = tid >> 5;
    if (tid == 0) carry = 0;
    __syncthreads();
    int nch = (n + CH - 1) / CH;
    for (int ch = 0; ch < nch; ++ch) {
        int i0 = ch * CH + tid * VPT;
        int p[VPT];
        int run = 0;
        #pragma unroll
        for (int k = 0; k < VPT; k++) {
            int idx = i0 + k;
            int v = (idx < n) ? (g_deg[idx] + 1) : 0;   // +1 = self loop
            run += v;
            p[k] = run;
        }
        int s = run;
        #pragma unroll
        for (int o = 1; o < 32; o <<= 1) {
            int t2 = __shfl_up_sync(0xffffffffu, s, o);
            if (lane >= o) s += t2;
        }
        if (lane == 31) wsum[w] = s;
        __syncthreads();
        if (w == 0) {
            int ws = wsum[lane];
            #pragma unroll
            for (int o = 1; o < 32; o <<= 1) {
                int t2 = __shfl_up_sync(0xffffffffu, ws, o);
                if (lane >= o) ws += t2;
            }
            wsum[lane] = ws;
        }
        __syncthreads();
        int base = carry + (w ? wsum[w - 1] : 0) + (s - run);
        #pragma unroll
        for (int k = 0; k < VPT; k++) {
            int idx = i0 + k;
            if (idx < n) g_offs[idx + 1] = base + p[k];
        }
        __syncthreads();
        if (tid == 1023) carry = base + run;
        __syncthreads();
    }
    if (threadIdx.x == 0) g_offs[0] = 0;
}

__global__ void k_fill(const int* __restrict__ ei, int E, int n) {
    int t = blockIdx.x * blockDim.x + threadIdx.x;
    if (t < n) g_deg[t] = 0;                    // deferred reset for next run
    if (t >= E + n) return;
    int s, d;
    if (t < E) { s = ei[t]; d = ei[E + t]; }
    else       { s = d = t - E; }               // self loop
    if (s < 0 || s >= n || d < 0 || d >= n) return;
    int pos = g_offs[d] + atomicAdd(&g_cur[d], 1);
    g_srcs[pos] = s;
}

// -------------------------------------------- per-node attention projections
__global__ void k_nodep(const float* __restrict__ x_ext, int x_sel,
                        const float* __restrict__ u,
                        const float* __restrict__ c, int K, int n) {
    int warp = (blockIdx.x * blockDim.x + threadIdx.x) >> 5;
    int lane = threadIdx.x & 31;
    if (warp >= n) return;
    const float* x = x_sel ? g_h : x_ext;
    const float* xr = x + (size_t)warp * K;
    float a0 = 0.f, a1 = 0.f, a2 = 0.f, a3 = 0.f;
    for (int k = lane; k < K; k += 32) {
        float xv = xr[k];
        float4 uv = ((const float4*)u)[k];
        a0 += xv * uv.x; a1 += xv * uv.y; a2 += xv * uv.z; a3 += xv * uv.w;
    }
    #pragma unroll
    for (int off = 16; off; off >>= 1) {
        a0 += __shfl_down_sync(0xffffffffu, a0, off);
        a1 += __shfl_down_sync(0xffffffffu, a1, off);
        a2 += __shfl_down_sync(0xffffffffu, a2, off);
        a3 += __shfl_down_sync(0xffffffffu, a3, off);
    }
    if (lane == 0) {
        float4 ea, eb;
        ea.x = expf(a0 + c[0]); ea.y = expf(a1 + c[1]);
        ea.z = expf(a2 + c[2]); ea.w = expf(a3 + c[3]);
        eb.x = expf(-a0); eb.y = expf(-a1); eb.z = expf(-a2); eb.w = expf(-a3);
        ((float4*)g_ea)[warp] = ea;
        ((float4*)g_eb)[warp] = eb;
    }
}

// -------------------------------------------------------- bf16 split utils
__device__ __forceinline__ uint32_t pack_bf16(float lo_elem, float hi_elem) {
    uint32_t r;
    asm("cvt.rn.bf16x2.f32 %0, %1, %2;" : "=r"(r) : "f"(hi_elem), "f"(lo_elem));
    return r;
}
__device__ __forceinline__ void split_pair(float f0, float f1,
                                           uint32_t& hw, uint32_t& lw) {
    hw = pack_bf16(f0, f1);
    float h0 = __uint_as_float(hw << 16);
    float h1 = __uint_as_float(hw & 0xffff0000u);
    lw = pack_bf16(f0 - h0, f1 - h1);
}

// ------------------------------------------------ input-space aggregation
__device__ __forceinline__ float4 fma4(float4 a, float s, float4 v) {
    a.x += s * v.x; a.y += s * v.y; a.z += s * v.z; a.w += s * v.w; return a;
}
__device__ __forceinline__ void store_split4(uint32_t* dh, uint32_t* dl, float4 r) {
    uint32_t h0, l0, h1, l1;
    split_pair(r.x, r.y, h0, l0);
    split_pair(r.z, r.w, h1, l1);
    *(uint2*)dh = make_uint2(h0, h1);
    *(uint2*)dl = make_uint2(l0, l1);
}

template<int IN, int ZC>
__global__ void k_agg_in(const float* __restrict__ x_ext, int x_sel, int n) {
    constexpr int V = IN / 128;
    int warp = (blockIdx.x * blockDim.x + threadIdx.x) >> 5;
    int lane = threadIdx.x & 31;
    if (warp >= n) return;
    const float* x = x_sel ? g_h : x_ext;
    int i  = warp;
    int s0 = g_offs[i], s1 = g_offs[i + 1];
    if (lane == 0) g_cur[i] = 0;                // deferred reset for next run
    float4 ebi = ((const float4*)g_eb)[i];

    float4 acc[4][V];
    #pragma unroll
    for (int h = 0; h < 4; h++)
        #pragma unroll
        for (int v = 0; v < V; v++) acc[h][v] = make_float4(0.f, 0.f, 0.f, 0.f);

    // software-pipelined edge loop: prefetch next index + ea + x row
    int j = (s0 < s1) ? g_srcs[s0] : 0;
    float4 a = ((const float4*)g_ea)[j];
    float4 xv[V];
    {
        const float4* xj = (const float4*)(x + (size_t)j * IN);
        #pragma unroll
        for (int v = 0; v < V; v++) xv[v] = (s0 < s1) ? xj[lane + 32 * v]
                                                      : make_float4(0.f,0.f,0.f,0.f);
    }
    for (int e = s0; e < s1; ++e) {
        int jn = 0; float4 an = a;
        float4 xvn[V];
        #pragma unroll
        for (int v = 0; v < V; v++) xvn[v] = xv[v];
        if (e + 1 < s1) {
            jn = g_srcs[e + 1];
            an = ((const float4*)g_ea)[jn];
            const float4* xjn = (const float4*)(x + (size_t)jn * IN);
            #pragma unroll
            for (int v = 0; v < V; v++) xvn[v] = xjn[lane + 32 * v];
        }
        float q0 = a.x * ebi.x, q1 = a.y * ebi.y, q2 = a.z * ebi.z, q3 = a.w * ebi.w;
        float rz = 1.0f / (q0 + q1 + q2 + q3);
        q0 *= rz; q1 *= rz; q2 *= rz; q3 *= rz;
        #pragma unroll
        for (int v = 0; v < V; v++) {
            acc[0][v] = fma4(acc[0][v], q0, xv[v]);
            acc[1][v] = fma4(acc[1][v], q1, xv[v]);
            acc[2][v] = fma4(acc[2][v], q2, xv[v]);
            acc[3][v] = fma4(acc[3][v], q3, xv[v]);
        }
        j = jn; a = an;
        #pragma unroll
        for (int v = 0; v < V; v++) xv[v] = xvn[v];
    }
    float inv = 1.0f / (float)(s1 - s0 > 0 ? s1 - s0 : 1);
    uint32_t* zh = g_yh + (size_t)i * 512;
    uint32_t* zl = g_yl + (size_t)i * 512;
    #pragma unroll
    for (int h = 0; h < 4; h++)
        #pragma unroll
        for (int v = 0; v < V; v++) {
            float4 r = acc[h][v];
            r.x *= inv; r.y *= inv; r.z *= inv; r.w *= inv;
            int wi = (h * IN) / 2 + 2 * (lane + 32 * v);
            store_split4(zh + wi, zl + wi, r);
        }
    if (ZC > 4 * IN) {
        const float4* xi = (const float4*)(x + (size_t)i * IN);
        #pragma unroll
        for (int v = 0; v < V; v++) {
            float4 r = xi[lane + 32 * v];
            int wi = 2 * IN + 2 * (lane + 32 * v);
            store_split4(zh + wi, zl + wi, r);
        }
    }
}

// ------------------------- fused stacked weight builder (both convs at once)
__global__ void k_wsplit(const float* __restrict__ W0,
                         const float* __restrict__ skipW0,
                         const float* __restrict__ W1) {
    int t = blockIdx.x * blockDim.x + threadIdx.x;
    if (t < 320 * 256) {
        int p = t >> 8, d = t & 255;
        float f[2];
        #pragma unroll
        for (int e = 0; e < 2; e++) {
            int r = 2 * p + e;
            if (r < 512) { int h = r >> 7, c = r & 127; f[e] = W0[c * 1024 + h * 256 + d]; }
            else         { int c = r - 512;             f[e] = skipW0[c * 256 + d]; }
        }
        uint32_t hw, lw;
        split_pair(f[0], f[1], hw, lw);
        g_wbh0[t] = hw; g_wbl0[t] = lw;
    }
    int t1 = t - 320 * 256;
    if (t1 >= 0 && t1 < 512 * 256) {
        int p = t1 >> 8, d = t1 & 255;
        float f[2];
        #pragma unroll
        for (int e = 0; e < 2; e++) {
            int r = 2 * p + e;
            int h = r >> 8, c = r & 255;
            f[e] = W1[c * 1024 + h * 256 + d];
        }
        uint32_t hw, lw;
        split_pair(f[0], f[1], hw, lw);
        g_wbh1[t1] = hw; g_wbl1[t1] = lw;
    }
}

// ----------------------------------------------------- bf16-split MMA GEMM
__device__ __forceinline__ void mma_bf16(float* c, const uint32_t* a, const uint32_t* b) {
    asm volatile(
        "mma.sync.aligned.m16n8k16.row.col.f32.bf16.bf16.f32 "
        "{%0,%1,%2,%3}, {%4,%5,%6,%7}, {%8,%9}, {%0,%1,%2,%3};"
        : "+f"(c[0]), "+f"(c[1]), "+f"(c[2]), "+f"(c[3])
        : "r"(a[0]), "r"(a[1]), "r"(a[2]), "r"(a[3]), "r"(b[0]), "r"(b[1]));
}
__device__ __forceinline__ void cp_async16(uint32_t smem_addr, const void* gptr) {
    asm volatile("cp.async.cg.shared.global [%0], [%1], 16;"
                 :: "r"(smem_addr), "l"(gptr));
}

// C = relu(A@B + b (+b2) (+g_h residual)).  A: g_yh/g_yl. B: g_wb*{0,1}.
// Tile 64(M) x 128(N) x 32(K), 2-stage cp.async pipeline in dynamic smem.
// 256 threads, 8 warps (2m x 4n), warp 32x32. grid (2, ceil(M/64)), occ 3.
#define AW 20
#define BW 136
#define ST_AH 0
#define ST_AL (64 * AW)
#define ST_BH (2 * 64 * AW)
#define ST_BL (2 * 64 * AW + 16 * BW)
#define STAGE_WORDS (2 * 64 * AW + 2 * 16 * BW)   // 6912 words = 27648 B
#define SMEM_BYTES (2 * STAGE_WORDS * 4)          // 55296 B

__global__ void __launch_bounds__(256, 3) k_mma(const float* __restrict__ b,
                                                const float* __restrict__ b2,
                                                int add_sel, int wsel,
                                                float* __restrict__ out_ext, int out_sel,
                                                int M, int K) {
    extern __shared__ uint32_t dyn[];
    float* C = out_sel ? out_ext : g_h;
    const uint32_t* WH = wsel ? g_wbh1 : g_wbh0;
    const uint32_t* WL = wsel ? g_wbl1 : g_wbl0;

    int tid = threadIdx.x;
    int wid = tid >> 5, lane = tid & 31;
    int g   = lane >> 2;
    int tig = lane & 3;
    int warp_m = (wid >> 2) * 32;
    int warp_n = (wid & 3) * 32;
    int m0 = blockIdx.y * 64;
    int n0 = blockIdx.x * 128;

    float acc[2][4][4];
    #pragma unroll
    for (int i = 0; i < 2; i++)
        #pragma unroll
        for (int j = 0; j < 4; j++)
            #pragma unroll
            for (int q = 0; q < 4; q++) acc[i][j][q] = 0.f;

    int arow = tid >> 2;
    int aseg = (tid & 3) * 4;
    bool a_ok = (m0 + arow) < M;
    int bp = tid >> 5;
    int bn = lane * 4;

    uint32_t base_s = (uint32_t)__cvta_generic_to_shared(dyn);
    uint32_t ah_s[2], al_s[2], bh0_s[2], bh1_s[2], bl0_s[2], bl1_s[2];
    #pragma unroll
    for (int st = 0; st < 2; st++) {
        uint32_t sb = base_s + st * (STAGE_WORDS * 4);
        ah_s[st]  = sb + (ST_AH + arow * AW + aseg) * 4;
        al_s[st]  = sb + (ST_AL + arow * AW + aseg) * 4;
        bh0_s[st] = sb + (ST_BH + bp * BW + bn) * 4;
        bh1_s[st] = sb + (ST_BH + (bp + 8) * BW + bn) * 4;
        bl0_s[st] = sb + (ST_BL + bp * BW + bn) * 4;
        bl1_s[st] = sb + (ST_BL + (bp + 8) * BW + bn) * 4;
    }

    int nsteps = K >> 5;

    auto issue = [&](int st, int step) {
        int k0 = step << 5;
        int gp0 = k0 >> 1;
        cp_async16(bh0_s[st], &WH[(gp0 + bp) * 256 + n0 + bn]);
        cp_async16(bh1_s[st], &WH[(gp0 + bp + 8) * 256 + n0 + bn]);
        cp_async16(bl0_s[st], &WL[(gp0 + bp) * 256 + n0 + bn]);
        cp_async16(bl1_s[st], &WL[(gp0 + bp + 8) * 256 + n0 + bn]);
        if (a_ok) {
            size_t gw = (size_t)(m0 + arow) * 512 + gp0 + aseg;
            cp_async16(ah_s[st], &g_yh[gw]);
            cp_async16(al_s[st], &g_yl[gw]);
        } else {
            uint32_t* st_base = dyn + st * STAGE_WORDS;
            *(uint4*)&st_base[ST_AH + arow * AW + aseg] = make_uint4(0, 0, 0, 0);
            *(uint4*)&st_base[ST_AL + arow * AW + aseg] = make_uint4(0, 0, 0, 0);
        }
        asm volatile("cp.async.commit_group;");
    };

    issue(0, 0);
    for (int s = 0; s < nsteps; s++) {
        int cur = s & 1;
        if (s + 1 < nsteps) {
            issue(cur ^ 1, s + 1);
            asm volatile("cp.async.wait_group 1;");
        } else {
            asm volatile("cp.async.wait_group 0;");
        }
        __syncthreads();

        const uint32_t* Ah = dyn + cur * STAGE_WORDS + ST_AH;
        const uint32_t* Al = dyn + cur * STAGE_WORDS + ST_AL;
        const uint32_t* Bh = dyn + cur * STAGE_WORDS + ST_BH;
        const uint32_t* Bl = dyn + cur * STAGE_WORDS + ST_BL;

        #pragma unroll
        for (int kk2 = 0; kk2 < 2; kk2++) {
            int K0 = kk2 * 8;
            uint32_t ah[2][4], al[2][4];
            #pragma unroll
            for (int mt = 0; mt < 2; mt++) {
                int mr = warp_m + mt * 16 + g;
                ah[mt][0] = Ah[(mr)     * AW + K0 + tig];
                ah[mt][1] = Ah[(mr + 8) * AW + K0 + tig];
                ah[mt][2] = Ah[(mr)     * AW + K0 + 4 + tig];
                ah[mt][3] = Ah[(mr + 8) * AW + K0 + 4 + tig];
                al[mt][0] = Al[(mr)     * AW + K0 + tig];
                al[mt][1] = Al[(mr + 8) * AW + K0 + tig];
                al[mt][2] = Al[(mr)     * AW + K0 + 4 + tig];
                al[mt][3] = Al[(mr + 8) * AW + K0 + 4 + tig];
            }
            #pragma unroll
            for (int nt = 0; nt < 4; nt++) {
                int nc = warp_n + nt * 8 + g;
                uint32_t bh[2], bl[2];
                bh[0] = Bh[(K0 + tig)     * BW + nc];
                bh[1] = Bh[(K0 + 4 + tig) * BW + nc];
                bl[0] = Bl[(K0 + tig)     * BW + nc];
                bl[1] = Bl[(K0 + 4 + tig) * BW + nc];
                #pragma unroll
                for (int mt = 0; mt < 2; mt++) {
                    mma_bf16(acc[mt][nt], ah[mt], bl);
                    mma_bf16(acc[mt][nt], al[mt], bh);
                    mma_bf16(acc[mt][nt], ah[mt], bh);
                }
            }
        }
        __syncthreads();
    }

    // ---- fused epilogue: bias (+bias2) (+residual) + relu ----
    #pragma unroll
    for (int mt = 0; mt < 2; mt++) {
        int r = m0 + warp_m + mt * 16 + g;
        #pragma unroll
        for (int nt = 0; nt < 4; nt++) {
            int cc = n0 + warp_n + nt * 8 + tig * 2;
            float bb0 = b[cc], bb1 = b[cc + 1];
            if (b2) { bb0 += b2[cc]; bb1 += b2[cc + 1]; }
            if (r < M) {
                float v0 = acc[mt][nt][0] + bb0;
                float v1 = acc[mt][nt][1] + bb1;
                if (add_sel) {
                    v0 += g_h[(size_t)r * 256 + cc];
                    v1 += g_h[(size_t)r * 256 + cc + 1];
                }
                C[(size_t)r * 256 + cc]     = fmaxf(v0, 0.f);
                C[(size_t)r * 256 + cc + 1] = fmaxf(v1, 0.f);
            }
            if (r + 8 < M) {
                float v2 = acc[mt][nt][2] + bb0;
                float v3 = acc[mt][nt][3] + bb1;
                if (add_sel) {
                    v2 += g_h[(size_t)(r + 8) * 256 + cc];
                    v3 += g_h[(size_t)(r + 8) * 256 + cc + 1];
                }
                C[(size_t)(r + 8) * 256 + cc]     = fmaxf(v2, 0.f);
                C[(size_t)(r + 8) * 256 + cc + 1] = fmaxf(v3, 0.f);
            }
        }
    }
}

// ---------------------------------------------------------------- launcher
extern "C" void kernel_launch(void* const* d_in, const int* in_sizes, int n_in,
                              void* d_out, int out_size) {
    const float* x      = (const float*)d_in[0];
    const int*   ei     = (const int*)d_in[1];     // int32 (JAX x64 disabled)
    const float* W0     = (const float*)d_in[2];
    const float* u0     = (const float*)d_in[3];
    const float* c0     = (const float*)d_in[4];
    const float* b0     = (const float*)d_in[5];
    const float* skipW0 = (const float*)d_in[6];
    const float* skipb0 = (const float*)d_in[7];
    const float* W1     = (const float*)d_in[8];
    const float* u1     = (const float*)d_in[9];
    const float* c1     = (const float*)d_in[10];
    const float* b1     = (const float*)d_in[11];

    int N = in_sizes[0] / 128;
    int E = in_sizes[1] / 2;
    if (N > MAXN || E > MAXE) return;

    float* out = (float*)d_out;

    cudaFuncSetAttribute(k_mma, cudaFuncAttributeMaxDynamicSharedMemorySize,
                         SMEM_BYTES);

    // weight pre-split (fused, independent of graph)
    k_wsplit<<<((320 + 512) * 256 + 255) / 256, 256>>>(W0, skipW0, W1);

    // CSR build: hist (+edge passthrough) -> scan -> fill (+deg reset)
    long long hElems = (long long)N * 256;
    int do_edges = ((long long)out_size - hElems >= 2LL * E) ? 1 : 0;
    k_hist_edges<<<(E + 255) / 256, 256>>>(ei, out + hElems, E, N, do_edges);
    k_scan<<<1, 1024>>>(N);
    k_fill<<<(E + N + 255) / 256, 256>>>(ei, E, N);

    // ---- conv0 ----
    k_nodep<<<(N * 32 + 255) / 256, 256>>>(x, 0, u0, c0, 128, N);
    k_agg_in<128, 640><<<(N * 32 + 255) / 256, 256>>>(x, 0, N);
    {   // g_h = relu(z[:,0:640] @ Wstack0 + b0 + skipb0)
        dim3 grid(2, (N + 63) / 64);
        k_mma<<<grid, 256, SMEM_BYTES>>>(b0, skipb0, 0, 0, (float*)nullptr, 0, N, 640);
    }

    // ---- conv1 ----
    k_nodep<<<(N * 32 + 255) / 256, 256>>>((const float*)nullptr, 1, u1, c1, 256, N);
    k_agg_in<256, 1024><<<(N * 32 + 255) / 256, 256>>>((const float*)nullptr, 1, N);
    {   // out = relu(z @ Wstack1 + b1 + g_h)
        dim3 grid(2, (N + 63) / 64);
        k_mma<<<grid, 256, SMEM_BYTES>>>(b1, (const float*)nullptr, 1, 1, out, 1, N, 1024);
    }
}

// round 14
// speedup vs baseline: 1.0128x; 1.0128x over previous
#include <cuda_runtime.h>
#include <cstdint>

// ---------------------------------------------------------------------------
// FeaStEncoderBlock, input-space aggregation + bf16-split tensor-core GEMM.
// Round 14: phase-0 mega-kernel. hist(+edge-copy), nodep(conv0) and wsplit
// are mutually independent -> merged into ONE launch with block-range
// dispatch, so their (atomic / FMA / copy)-bound phases overlap across SMs
// instead of serializing on the stream. Serial chain: phase0 -> scan -> fill
// -> agg0 -> mma0 -> nodep1 -> agg1 -> mma1  (8 launches).
// GEMM frozen (HMMA roofline); agg frozen (L2-BW floor).
// ---------------------------------------------------------------------------

#define MAXN 20000
#define MAXE 320000

__device__ __align__(16) uint32_t g_yh[(size_t)MAXN * 512];   // z hi pair-words
__device__ __align__(16) uint32_t g_yl[(size_t)MAXN * 512];   // z lo pair-words
__device__ __align__(16) float    g_h[(size_t)MAXN * 256];    // hidden h
__device__ __align__(16) uint32_t g_wbh0[320 * 256];          // conv0 W hi
__device__ __align__(16) uint32_t g_wbl0[320 * 256];          // conv0 W lo
__device__ __align__(16) uint32_t g_wbh1[512 * 256];          // conv1 W hi
__device__ __align__(16) uint32_t g_wbl1[512 * 256];          // conv1 W lo
__device__ __align__(16) float    g_ea[MAXN * 4];
__device__ __align__(16) float    g_eb[MAXN * 4];
__device__ int g_deg[MAXN];        // zeroed at load; re-zeroed by k_fill
__device__ int g_cur[MAXN];        // zeroed at load; re-zeroed by k_agg_in
__device__ int g_offs[MAXN + 1];
__device__ int g_srcs[MAXN + MAXE];

// -------------------------------------------------------- bf16 split utils
__device__ __forceinline__ uint32_t pack_bf16(float lo_elem, float hi_elem) {
    uint32_t r;
    asm("cvt.rn.bf16x2.f32 %0, %1, %2;" : "=r"(r) : "f"(hi_elem), "f"(lo_elem));
    return r;
}
__device__ __forceinline__ void split_pair(float f0, float f1,
                                           uint32_t& hw, uint32_t& lw) {
    hw = pack_bf16(f0, f1);
    float h0 = __uint_as_float(hw << 16);
    float h1 = __uint_as_float(hw & 0xffff0000u);
    lw = pack_bf16(f0 - h0, f1 - h1);
}

// ------------------------------------------ nodep body (shared conv0/conv1)
__device__ __forceinline__ void nodep_body(int warp, int lane,
                                           const float* __restrict__ x,
                                           const float* __restrict__ u,
                                           const float* __restrict__ c,
                                           int K, int n) {
    if (warp >= n) return;
    const float* xr = x + (size_t)warp * K;
    float a0 = 0.f, a1 = 0.f, a2 = 0.f, a3 = 0.f;
    for (int k = lane; k < K; k += 32) {
        float xv = xr[k];
        float4 uv = ((const float4*)u)[k];
        a0 += xv * uv.x; a1 += xv * uv.y; a2 += xv * uv.z; a3 += xv * uv.w;
    }
    #pragma unroll
    for (int off = 16; off; off >>= 1) {
        a0 += __shfl_down_sync(0xffffffffu, a0, off);
        a1 += __shfl_down_sync(0xffffffffu, a1, off);
        a2 += __shfl_down_sync(0xffffffffu, a2, off);
        a3 += __shfl_down_sync(0xffffffffu, a3, off);
    }
    if (lane == 0) {
        float4 ea, eb;
        ea.x = expf(a0 + c[0]); ea.y = expf(a1 + c[1]);
        ea.z = expf(a2 + c[2]); ea.w = expf(a3 + c[3]);
        eb.x = expf(-a0); eb.y = expf(-a1); eb.z = expf(-a2); eb.w = expf(-a3);
        ((float4*)g_ea)[warp] = ea;
        ((float4*)g_eb)[warp] = eb;
    }
}

// ------------------- phase-0 mega-kernel: hist+edges | nodep(conv0) | wsplit
// blocks [0,HB): histogram + edge passthrough (E threads)
// blocks [HB,HB+NB): attention projections for conv0 (N warps)
// blocks [HB+NB, ...): stacked-weight bf16 pre-split (both convs)
__global__ void k_phase0(const int* __restrict__ ei,
                         float* __restrict__ out_edges,
                         int E, int n, int do_edges,
                         const float* __restrict__ x,
                         const float* __restrict__ u0,
                         const float* __restrict__ c0,
                         const float* __restrict__ W0,
                         const float* __restrict__ skipW0,
                         const float* __restrict__ W1,
                         int HB, int NB) {
    int b = blockIdx.x;
    if (b < HB) {
        // ---- histogram + edge passthrough ----
        int t = b * 256 + threadIdx.x;
        if (t >= E) return;
        int s = ei[t], d = ei[E + t];
        if (do_edges) {
            out_edges[t]     = (float)s;
            out_edges[E + t] = (float)d;
        }
        if (d >= 0 && d < n) atomicAdd(&g_deg[d], 1);
    } else if (b < HB + NB) {
        // ---- nodep conv0 (K=128) ----
        int warp = ((b - HB) * 256 + threadIdx.x) >> 5;
        int lane = threadIdx.x & 31;
        nodep_body(warp, lane, x, u0, c0, 128, n);
    } else {
        // ---- weight pre-split ----
        int t = (b - HB - NB) * 256 + threadIdx.x;
        if (t < 320 * 256) {
            int p = t >> 8, d = t & 255;
            float f[2];
            #pragma unroll
            for (int e = 0; e < 2; e++) {
                int r = 2 * p + e;
                if (r < 512) { int h = r >> 7, c = r & 127; f[e] = W0[c * 1024 + h * 256 + d]; }
                else         { int c = r - 512;             f[e] = skipW0[c * 256 + d]; }
            }
            uint32_t hw, lw;
            split_pair(f[0], f[1], hw, lw);
            g_wbh0[t] = hw; g_wbl0[t] = lw;
        }
        int t1 = t - 320 * 256;
        if (t1 >= 0 && t1 < 512 * 256) {
            int p = t1 >> 8, d = t1 & 255;
            float f[2];
            #pragma unroll
            for (int e = 0; e < 2; e++) {
                int r = 2 * p + e;
                int h = r >> 8, c = r & 255;
                f[e] = W1[c * 1024 + h * 256 + d];
            }
            uint32_t hw, lw;
            split_pair(f[0], f[1], hw, lw);
            g_wbh1[t1] = hw; g_wbl1[t1] = lw;
        }
    }
}

// single-block exclusive scan; 10 preloaded values/thread (self-loop +1 folded)
__global__ void k_scan(int n) {
    __shared__ int wsum[32];
    __shared__ int carry;
    const int VPT = 10;
    const int CH  = 1024 * VPT;
    int tid = threadIdx.x, lane = tid & 31, w = tid >> 5;
    if (tid == 0) carry = 0;
    __syncthreads();
    int nch = (n + CH - 1) / CH;
    for (int ch = 0; ch < nch; ++ch) {
        int i0 = ch * CH + tid * VPT;
        int p[VPT];
        int run = 0;
        #pragma unroll
        for (int k = 0; k < VPT; k++) {
            int idx = i0 + k;
            int v = (idx < n) ? (g_deg[idx] + 1) : 0;   // +1 = self loop
            run += v;
            p[k] = run;
        }
        int s = run;
        #pragma unroll
        for (int o = 1; o < 32; o <<= 1) {
            int t2 = __shfl_up_sync(0xffffffffu, s, o);
            if (lane >= o) s += t2;
        }
        if (lane == 31) wsum[w] = s;
        __syncthreads();
        if (w == 0) {
            int ws = wsum[lane];
            #pragma unroll
            for (int o = 1; o < 32; o <<= 1) {
                int t2 = __shfl_up_sync(0xffffffffu, ws, o);
                if (lane >= o) ws += t2;
            }
            wsum[lane] = ws;
        }
        __syncthreads();
        int base = carry + (w ? wsum[w - 1] : 0) + (s - run);
        #pragma unroll
        for (int k = 0; k < VPT; k++) {
            int idx = i0 + k;
            if (idx < n) g_offs[idx + 1] = base + p[k];
        }
        __syncthreads();
        if (tid == 1023) carry = base + run;
        __syncthreads();
    }
    if (threadIdx.x == 0) g_offs[0] = 0;
}

__global__ void k_fill(const int* __restrict__ ei, int E, int n) {
    int t = blockIdx.x * blockDim.x + threadIdx.x;
    if (t < n) g_deg[t] = 0;                    // deferred reset for next run
    if (t >= E + n) return;
    int s, d;
    if (t < E) { s = ei[t]; d = ei[E + t]; }
    else       { s = d = t - E; }               // self loop
    if (s < 0 || s >= n || d < 0 || d >= n) return;
    int pos = g_offs[d] + atomicAdd(&g_cur[d], 1);
    g_srcs[pos] = s;
}

// ------------------------------------- standalone nodep (conv1, depends on h)
__global__ void k_nodep(const float* __restrict__ u,
                        const float* __restrict__ c, int K, int n) {
    int warp = (blockIdx.x * blockDim.x + threadIdx.x) >> 5;
    int lane = threadIdx.x & 31;
    nodep_body(warp, lane, g_h, u, c, K, n);
}

// ------------------------------------------------ input-space aggregation
__device__ __forceinline__ float4 fma4(float4 a, float s, float4 v) {
    a.x += s * v.x; a.y += s * v.y; a.z += s * v.z; a.w += s * v.w; return a;
}
__device__ __forceinline__ void store_split4(uint32_t* dh, uint32_t* dl, float4 r) {
    uint32_t h0, l0, h1, l1;
    split_pair(r.x, r.y, h0, l0);
    split_pair(r.z, r.w, h1, l1);
    *(uint2*)dh = make_uint2(h0, h1);
    *(uint2*)dl = make_uint2(l0, l1);
}

template<int IN, int ZC>
__global__ void k_agg_in(const float* __restrict__ x_ext, int x_sel, int n) {
    constexpr int V = IN / 128;
    int warp = (blockIdx.x * blockDim.x + threadIdx.x) >> 5;
    int lane = threadIdx.x & 31;
    if (warp >= n) return;
    const float* x = x_sel ? g_h : x_ext;
    int i  = warp;
    int s0 = g_offs[i], s1 = g_offs[i + 1];
    if (lane == 0) g_cur[i] = 0;                // deferred reset for next run
    float4 ebi = ((const float4*)g_eb)[i];

    float4 acc[4][V];
    #pragma unroll
    for (int h = 0; h < 4; h++)
        #pragma unroll
        for (int v = 0; v < V; v++) acc[h][v] = make_float4(0.f, 0.f, 0.f, 0.f);

    // software-pipelined edge loop: prefetch next index + ea + x row
    int j = (s0 < s1) ? g_srcs[s0] : 0;
    float4 a = ((const float4*)g_ea)[j];
    float4 xv[V];
    {
        const float4* xj = (const float4*)(x + (size_t)j * IN);
        #pragma unroll
        for (int v = 0; v < V; v++) xv[v] = (s0 < s1) ? xj[lane + 32 * v]
                                                      : make_float4(0.f,0.f,0.f,0.f);
    }
    for (int e = s0; e < s1; ++e) {
        int jn = 0; float4 an = a;
        float4 xvn[V];
        #pragma unroll
        for (int v = 0; v < V; v++) xvn[v] = xv[v];
        if (e + 1 < s1) {
            jn = g_srcs[e + 1];
            an = ((const float4*)g_ea)[jn];
            const float4* xjn = (const float4*)(x + (size_t)jn * IN);
            #pragma unroll
            for (int v = 0; v < V; v++) xvn[v] = xjn[lane + 32 * v];
        }
        float q0 = a.x * ebi.x, q1 = a.y * ebi.y, q2 = a.z * ebi.z, q3 = a.w * ebi.w;
        float rz = 1.0f / (q0 + q1 + q2 + q3);
        q0 *= rz; q1 *= rz; q2 *= rz; q3 *= rz;
        #pragma unroll
        for (int v = 0; v < V; v++) {
            acc[0][v] = fma4(acc[0][v], q0, xv[v]);
            acc[1][v] = fma4(acc[1][v], q1, xv[v]);
            acc[2][v] = fma4(acc[2][v], q2, xv[v]);
            acc[3][v] = fma4(acc[3][v], q3, xv[v]);
        }
        j = jn; a = an;
        #pragma unroll
        for (int v = 0; v < V; v++) xv[v] = xvn[v];
    }
    float inv = 1.0f / (float)(s1 - s0 > 0 ? s1 - s0 : 1);
    uint32_t* zh = g_yh + (size_t)i * 512;
    uint32_t* zl = g_yl + (size_t)i * 512;
    #pragma unroll
    for (int h = 0; h < 4; h++)
        #pragma unroll
        for (int v = 0; v < V; v++) {
            float4 r = acc[h][v];
            r.x *= inv; r.y *= inv; r.z *= inv; r.w *= inv;
            int wi = (h * IN) / 2 + 2 * (lane + 32 * v);
            store_split4(zh + wi, zl + wi, r);
        }
    if (ZC > 4 * IN) {
        const float4* xi = (const float4*)(x + (size_t)i * IN);
        #pragma unroll
        for (int v = 0; v < V; v++) {
            float4 r = xi[lane + 32 * v];
            int wi = 2 * IN + 2 * (lane + 32 * v);
            store_split4(zh + wi, zl + wi, r);
        }
    }
}

// ----------------------------------------------------- bf16-split MMA GEMM
__device__ __forceinline__ void mma_bf16(float* c, const uint32_t* a, const uint32_t* b) {
    asm volatile(
        "mma.sync.aligned.m16n8k16.row.col.f32.bf16.bf16.f32 "
        "{%0,%1,%2,%3}, {%4,%5,%6,%7}, {%8,%9}, {%0,%1,%2,%3};"
        : "+f"(c[0]), "+f"(c[1]), "+f"(c[2]), "+f"(c[3])
        : "r"(a[0]), "r"(a[1]), "r"(a[2]), "r"(a[3]), "r"(b[0]), "r"(b[1]));
}
__device__ __forceinline__ void cp_async16(uint32_t smem_addr, const void* gptr) {
    asm volatile("cp.async.cg.shared.global [%0], [%1], 16;"
                 :: "r"(smem_addr), "l"(gptr));
}

// C = relu(A@B + b (+b2) (+g_h residual)).  A: g_yh/g_yl. B: g_wb*{0,1}.
// Tile 64(M) x 128(N) x 32(K), 2-stage cp.async pipeline in dynamic smem.
// 256 threads, 8 warps (2m x 4n), warp 32x32. grid (2, ceil(M/64)), occ 3.
#define AW 20
#define BW 136
#define ST_AH 0
#define ST_AL (64 * AW)
#define ST_BH (2 * 64 * AW)
#define ST_BL (2 * 64 * AW + 16 * BW)
#define STAGE_WORDS (2 * 64 * AW + 2 * 16 * BW)   // 6912 words = 27648 B
#define SMEM_BYTES (2 * STAGE_WORDS * 4)          // 55296 B

__global__ void __launch_bounds__(256, 3) k_mma(const float* __restrict__ b,
                                                const float* __restrict__ b2,
                                                int add_sel, int wsel,
                                                float* __restrict__ out_ext, int out_sel,
                                                int M, int K) {
    extern __shared__ uint32_t dyn[];
    float* C = out_sel ? out_ext : g_h;
    const uint32_t* WH = wsel ? g_wbh1 : g_wbh0;
    const uint32_t* WL = wsel ? g_wbl1 : g_wbl0;

    int tid = threadIdx.x;
    int wid = tid >> 5, lane = tid & 31;
    int g   = lane >> 2;
    int tig = lane & 3;
    int warp_m = (wid >> 2) * 32;
    int warp_n = (wid & 3) * 32;
    int m0 = blockIdx.y * 64;
    int n0 = blockIdx.x * 128;

    float acc[2][4][4];
    #pragma unroll
    for (int i = 0; i < 2; i++)
        #pragma unroll
        for (int j = 0; j < 4; j++)
            #pragma unroll
            for (int q = 0; q < 4; q++) acc[i][j][q] = 0.f;

    int arow = tid >> 2;
    int aseg = (tid & 3) * 4;
    bool a_ok = (m0 + arow) < M;
    int bp = tid >> 5;
    int bn = lane * 4;

    uint32_t base_s = (uint32_t)__cvta_generic_to_shared(dyn);
    uint32_t ah_s[2], al_s[2], bh0_s[2], bh1_s[2], bl0_s[2], bl1_s[2];
    #pragma unroll
    for (int st = 0; st < 2; st++) {
        uint32_t sb = base_s + st * (STAGE_WORDS * 4);
        ah_s[st]  = sb + (ST_AH + arow * AW + aseg) * 4;
        al_s[st]  = sb + (ST_AL + arow * AW + aseg) * 4;
        bh0_s[st] = sb + (ST_BH + bp * BW + bn) * 4;
        bh1_s[st] = sb + (ST_BH + (bp + 8) * BW + bn) * 4;
        bl0_s[st] = sb + (ST_BL + bp * BW + bn) * 4;
        bl1_s[st] = sb + (ST_BL + (bp + 8) * BW + bn) * 4;
    }

    int nsteps = K >> 5;

    auto issue = [&](int st, int step) {
        int k0 = step << 5;
        int gp0 = k0 >> 1;
        cp_async16(bh0_s[st], &WH[(gp0 + bp) * 256 + n0 + bn]);
        cp_async16(bh1_s[st], &WH[(gp0 + bp + 8) * 256 + n0 + bn]);
        cp_async16(bl0_s[st], &WL[(gp0 + bp) * 256 + n0 + bn]);
        cp_async16(bl1_s[st], &WL[(gp0 + bp + 8) * 256 + n0 + bn]);
        if (a_ok) {
            size_t gw = (size_t)(m0 + arow) * 512 + gp0 + aseg;
            cp_async16(ah_s[st], &g_yh[gw]);
            cp_async16(al_s[st], &g_yl[gw]);
        } else {
            uint32_t* st_base = dyn + st * STAGE_WORDS;
            *(uint4*)&st_base[ST_AH + arow * AW + aseg] = make_uint4(0, 0, 0, 0);
            *(uint4*)&st_base[ST_AL + arow * AW + aseg] = make_uint4(0, 0, 0, 0);
        }
        asm volatile("cp.async.commit_group;");
    };

    issue(0, 0);
    for (int s = 0; s < nsteps; s++) {
        int cur = s & 1;
        if (s + 1 < nsteps) {
            issue(cur ^ 1, s + 1);
            asm volatile("cp.async.wait_group 1;");
        } else {
            asm volatile("cp.async.wait_group 0;");
        }
        __syncthreads();

        const uint32_t* Ah = dyn + cur * STAGE_WORDS + ST_AH;
        const uint32_t* Al = dyn + cur * STAGE_WORDS + ST_AL;
        const uint32_t* Bh = dyn + cur * STAGE_WORDS + ST_BH;
        const uint32_t* Bl = dyn + cur * STAGE_WORDS + ST_BL;

        #pragma unroll
        for (int kk2 = 0; kk2 < 2; kk2++) {
            int K0 = kk2 * 8;
            uint32_t ah[2][4], al[2][4];
            #pragma unroll
            for (int mt = 0; mt < 2; mt++) {
                int mr = warp_m + mt * 16 + g;
                ah[mt][0] = Ah[(mr)     * AW + K0 + tig];
                ah[mt][1] = Ah[(mr + 8) * AW + K0 + tig];
                ah[mt][2] = Ah[(mr)     * AW + K0 + 4 + tig];
                ah[mt][3] = Ah[(mr + 8) * AW + K0 + 4 + tig];
                al[mt][0] = Al[(mr)     * AW + K0 + tig];
                al[mt][1] = Al[(mr + 8) * AW + K0 + tig];
                al[mt][2] = Al[(mr)     * AW + K0 + 4 + tig];
                al[mt][3] = Al[(mr + 8) * AW + K0 + 4 + tig];
            }
            #pragma unroll
            for (int nt = 0; nt < 4; nt++) {
                int nc = warp_n + nt * 8 + g;
                uint32_t bh[2], bl[2];
                bh[0] = Bh[(K0 + tig)     * BW + nc];
                bh[1] = Bh[(K0 + 4 + tig) * BW + nc];
                bl[0] = Bl[(K0 + tig)     * BW + nc];
                bl[1] = Bl[(K0 + 4 + tig) * BW + nc];
                #pragma unroll
                for (int mt = 0; mt < 2; mt++) {
                    mma_bf16(acc[mt][nt], ah[mt], bl);
                    mma_bf16(acc[mt][nt], al[mt], bh);
                    mma_bf16(acc[mt][nt], ah[mt], bh);
                }
            }
        }
        __syncthreads();
    }

    // ---- fused epilogue: bias (+bias2) (+residual) + relu ----
    #pragma unroll
    for (int mt = 0; mt < 2; mt++) {
        int r = m0 + warp_m + mt * 16 + g;
        #pragma unroll
        for (int nt = 0; nt < 4; nt++) {
            int cc = n0 + warp_n + nt * 8 + tig * 2;
            float bb0 = b[cc], bb1 = b[cc + 1];
            if (b2) { bb0 += b2[cc]; bb1 += b2[cc + 1]; }
            if (r < M) {
                float v0 = acc[mt][nt][0] + bb0;
                float v1 = acc[mt][nt][1] + bb1;
                if (add_sel) {
                    v0 += g_h[(size_t)r * 256 + cc];
                    v1 += g_h[(size_t)r * 256 + cc + 1];
                }
                C[(size_t)r * 256 + cc]     = fmaxf(v0, 0.f);
                C[(size_t)r * 256 + cc + 1] = fmaxf(v1, 0.f);
            }
            if (r + 8 < M) {
                float v2 = acc[mt][nt][2] + bb0;
                float v3 = acc[mt][nt][3] + bb1;
                if (add_sel) {
                    v2 += g_h[(size_t)(r + 8) * 256 + cc];
                    v3 += g_h[(size_t)(r + 8) * 256 + cc + 1];
                }
                C[(size_t)(r + 8) * 256 + cc]     = fmaxf(v2, 0.f);
                C[(size_t)(r + 8) * 256 + cc + 1] = fmaxf(v3, 0.f);
            }
        }
    }
}

// ---------------------------------------------------------------- launcher
extern "C" void kernel_launch(void* const* d_in, const int* in_sizes, int n_in,
                              void* d_out, int out_size) {
    const float* x      = (const float*)d_in[0];
    const int*   ei     = (const int*)d_in[1];     // int32 (JAX x64 disabled)
    const float* W0     = (const float*)d_in[2];
    const float* u0     = (const float*)d_in[3];
    const float* c0     = (const float*)d_in[4];
    const float* b0     = (const float*)d_in[5];
    const float* skipW0 = (const float*)d_in[6];
    const float* skipb0 = (const float*)d_in[7];
    const float* W1     = (const float*)d_in[8];
    const float* u1     = (const float*)d_in[9];
    const float* c1     = (const float*)d_in[10];
    const float* b1     = (const float*)d_in[11];

    int N = in_sizes[0] / 128;
    int E = in_sizes[1] / 2;
    if (N > MAXN || E > MAXE) return;

    float* out = (float*)d_out;

    cudaFuncSetAttribute(k_mma, cudaFuncAttributeMaxDynamicSharedMemorySize,
                         SMEM_BYTES);

    // phase 0: hist(+edge passthrough) | nodep(conv0) | wsplit -- one launch
    long long hElems = (long long)N * 256;
    int do_edges = ((long long)out_size - hElems >= 2LL * E) ? 1 : 0;
    int HB = (E + 255) / 256;
    int NB = (N * 32 + 255) / 256;
    int WB = ((320 + 512) * 256 + 255) / 256;
    k_phase0<<<HB + NB + WB, 256>>>(ei, out + hElems, E, N, do_edges,
                                    x, u0, c0, W0, skipW0, W1, HB, NB);

    // CSR: scan -> fill (+deg reset)
    k_scan<<<1, 1024>>>(N);
    k_fill<<<(E + N + 255) / 256, 256>>>(ei, E, N);

    // ---- conv0 ----
    k_agg_in<128, 640><<<(N * 32 + 255) / 256, 256>>>(x, 0, N);
    {   // g_h = relu(z[:,0:640] @ Wstack0 + b0 + skipb0)
        dim3 grid(2, (N + 63) / 64);
        k_mma<<<grid, 256, SMEM_BYTES>>>(b0, skipb0, 0, 0, (float*)nullptr, 0, N, 640);
    }

    // ---- conv1 ----
    k_nodep<<<(N * 32 + 255) / 256, 256>>>(u1, c1, 256, N);
    k_agg_in<256, 1024><<<(N * 32 + 255) / 256, 256>>>((const float*)nullptr, 1, N);
    {   // out = relu(z @ Wstack1 + b1 + g_h)
        dim3 grid(2, (N + 63) / 64);
        k_mma<<<grid, 256, SMEM_BYTES>>>(b1, (const float*)nullptr, 1, 1, out, 1, N, 1024);
    }
}

// round 15
// speedup vs baseline: 1.0321x; 1.0191x over previous
#include <cuda_runtime.h>
#include <cstdint>

// ---------------------------------------------------------------------------
// FeaStEncoderBlock, input-space aggregation + bf16-split tensor-core GEMM.
// Round 15: per-edge attention weights PRECOMPUTED (q = softmax * 1/deg,
// stored per CSR slot). The agg hot loop loses the 32x-redundant per-lane
// softmax (12 ALU ops + MUFU per edge-lane) -> pure gather + FMA.
//   conv0 q: computed inside k_fill (ea/eb ready; fill has idle ALU)
//   conv1 q: thread-per-edge k_edgeq1 (g_dsts stored by fill)
// GEMM frozen (HMMA roofline).
// ---------------------------------------------------------------------------

#define MAXN 20000
#define MAXE 320000

__device__ __align__(16) uint32_t g_yh[(size_t)MAXN * 512];   // z hi pair-words
__device__ __align__(16) uint32_t g_yl[(size_t)MAXN * 512];   // z lo pair-words
__device__ __align__(16) float    g_h[(size_t)MAXN * 256];    // hidden h
__device__ __align__(16) uint32_t g_wbh0[320 * 256];          // conv0 W hi
__device__ __align__(16) uint32_t g_wbl0[320 * 256];          // conv0 W lo
__device__ __align__(16) uint32_t g_wbh1[512 * 256];          // conv1 W hi
__device__ __align__(16) uint32_t g_wbl1[512 * 256];          // conv1 W lo
__device__ __align__(16) float    g_ea[MAXN * 4];
__device__ __align__(16) float    g_eb[MAXN * 4];
__device__ __align__(16) float    g_q[(size_t)(MAXN + MAXE) * 4]; // per-slot q
__device__ int g_deg[MAXN];        // zeroed at load; re-zeroed by k_fill
__device__ int g_cur[MAXN];        // zeroed at load; re-zeroed by k_agg_in
__device__ int g_offs[MAXN + 1];
__device__ int g_srcs[MAXN + MAXE];
__device__ int g_dsts[MAXN + MAXE];

// -------------------------------------------------------- bf16 split utils
__device__ __forceinline__ uint32_t pack_bf16(float lo_elem, float hi_elem) {
    uint32_t r;
    asm("cvt.rn.bf16x2.f32 %0, %1, %2;" : "=r"(r) : "f"(hi_elem), "f"(lo_elem));
    return r;
}
__device__ __forceinline__ void split_pair(float f0, float f1,
                                           uint32_t& hw, uint32_t& lw) {
    hw = pack_bf16(f0, f1);
    float h0 = __uint_as_float(hw << 16);
    float h1 = __uint_as_float(hw & 0xffff0000u);
    lw = pack_bf16(f0 - h0, f1 - h1);
}

// ----------------------------------------------------- per-edge q compute
__device__ __forceinline__ float4 edge_q(int s, int d, float inv) {
    float4 ea = ((const float4*)g_ea)[s];
    float4 eb = ((const float4*)g_eb)[d];
    float q0 = ea.x * eb.x, q1 = ea.y * eb.y, q2 = ea.z * eb.z, q3 = ea.w * eb.w;
    float rz = inv / (q0 + q1 + q2 + q3);
    return make_float4(q0 * rz, q1 * rz, q2 * rz, q3 * rz);
}

// ------------------------------------------ nodep body (shared conv0/conv1)
__device__ __forceinline__ void nodep_body(int warp, int lane,
                                           const float* __restrict__ x,
                                           const float* __restrict__ u,
                                           const float* __restrict__ c,
                                           int K, int n) {
    if (warp >= n) return;
    const float* xr = x + (size_t)warp * K;
    float a0 = 0.f, a1 = 0.f, a2 = 0.f, a3 = 0.f;
    for (int k = lane; k < K; k += 32) {
        float xv = xr[k];
        float4 uv = ((const float4*)u)[k];
        a0 += xv * uv.x; a1 += xv * uv.y; a2 += xv * uv.z; a3 += xv * uv.w;
    }
    #pragma unroll
    for (int off = 16; off; off >>= 1) {
        a0 += __shfl_down_sync(0xffffffffu, a0, off);
        a1 += __shfl_down_sync(0xffffffffu, a1, off);
        a2 += __shfl_down_sync(0xffffffffu, a2, off);
        a3 += __shfl_down_sync(0xffffffffu, a3, off);
    }
    if (lane == 0) {
        float4 ea, eb;
        ea.x = expf(a0 + c[0]); ea.y = expf(a1 + c[1]);
        ea.z = expf(a2 + c[2]); ea.w = expf(a3 + c[3]);
        eb.x = expf(-a0); eb.y = expf(-a1); eb.z = expf(-a2); eb.w = expf(-a3);
        ((float4*)g_ea)[warp] = ea;
        ((float4*)g_eb)[warp] = eb;
    }
}

// ------------------- phase-0 mega-kernel: hist+edges | nodep(conv0) | wsplit
__global__ void k_phase0(const int* __restrict__ ei,
                         float* __restrict__ out_edges,
                         int E, int n, int do_edges,
                         const float* __restrict__ x,
                         const float* __restrict__ u0,
                         const float* __restrict__ c0,
                         const float* __restrict__ W0,
                         const float* __restrict__ skipW0,
                         const float* __restrict__ W1,
                         int HB, int NB) {
    int b = blockIdx.x;
    if (b < HB) {
        int t = b * 256 + threadIdx.x;
        if (t >= E) return;
        int s = ei[t], d = ei[E + t];
        if (do_edges) {
            out_edges[t]     = (float)s;
            out_edges[E + t] = (float)d;
        }
        if (d >= 0 && d < n) atomicAdd(&g_deg[d], 1);
    } else if (b < HB + NB) {
        int warp = ((b - HB) * 256 + threadIdx.x) >> 5;
        int lane = threadIdx.x & 31;
        nodep_body(warp, lane, x, u0, c0, 128, n);
    } else {
        int t = (b - HB - NB) * 256 + threadIdx.x;
        if (t < 320 * 256) {
            int p = t >> 8, d = t & 255;
            float f[2];
            #pragma unroll
            for (int e = 0; e < 2; e++) {
                int r = 2 * p + e;
                if (r < 512) { int h = r >> 7, c = r & 127; f[e] = W0[c * 1024 + h * 256 + d]; }
                else         { int c = r - 512;             f[e] = skipW0[c * 256 + d]; }
            }
            uint32_t hw, lw;
            split_pair(f[0], f[1], hw, lw);
            g_wbh0[t] = hw; g_wbl0[t] = lw;
        }
        int t1 = t - 320 * 256;
        if (t1 >= 0 && t1 < 512 * 256) {
            int p = t1 >> 8, d = t1 & 255;
            float f[2];
            #pragma unroll
            for (int e = 0; e < 2; e++) {
                int r = 2 * p + e;
                int h = r >> 8, c = r & 255;
                f[e] = W1[c * 1024 + h * 256 + d];
            }
            uint32_t hw, lw;
            split_pair(f[0], f[1], hw, lw);
            g_wbh1[t1] = hw; g_wbl1[t1] = lw;
        }
    }
}

// single-block exclusive scan; 10 preloaded values/thread (self-loop +1 folded)
__global__ void k_scan(int n) {
    __shared__ int wsum[32];
    __shared__ int carry;
    const int VPT = 10;
    const int CH  = 1024 * VPT;
    int tid = threadIdx.x, lane = tid & 31, w = tid >> 5;
    if (tid == 0) carry = 0;
    __syncthreads();
    int nch = (n + CH - 1) / CH;
    for (int ch = 0; ch < nch; ++ch) {
        int i0 = ch * CH + tid * VPT;
        int p[VPT];
        int run = 0;
        #pragma unroll
        for (int k = 0; k < VPT; k++) {
            int idx = i0 + k;
            int v = (idx < n) ? (g_deg[idx] + 1) : 0;   // +1 = self loop
            run += v;
            p[k] = run;
        }
        int s = run;
        #pragma unroll
        for (int o = 1; o < 32; o <<= 1) {
            int t2 = __shfl_up_sync(0xffffffffu, s, o);
            if (lane >= o) s += t2;
        }
        if (lane == 31) wsum[w] = s;
        __syncthreads();
        if (w == 0) {
            int ws = wsum[lane];
            #pragma unroll
            for (int o = 1; o < 32; o <<= 1) {
                int t2 = __shfl_up_sync(0xffffffffu, ws, o);
                if (lane >= o) ws += t2;
            }
            wsum[lane] = ws;
        }
        __syncthreads();
        int base = carry + (w ? wsum[w - 1] : 0) + (s - run);
        #pragma unroll
        for (int k = 0; k < VPT; k++) {
            int idx = i0 + k;
            if (idx < n) g_offs[idx + 1] = base + p[k];
        }
        __syncthreads();
        if (tid == 1023) carry = base + run;
        __syncthreads();
    }
    if (threadIdx.x == 0) g_offs[0] = 0;
}

// fill CSR + compute conv0 per-edge q (ea/eb ready from phase0)
__global__ void k_fill(const int* __restrict__ ei, int E, int n) {
    int t = blockIdx.x * blockDim.x + threadIdx.x;
    if (t < n) g_deg[t] = 0;                    // deferred reset for next run
    if (t >= E + n) return;
    int s, d;
    if (t < E) { s = ei[t]; d = ei[E + t]; }
    else       { s = d = t - E; }               // self loop
    if (s < 0 || s >= n || d < 0 || d >= n) return;
    int o0 = g_offs[d];
    int pos = o0 + atomicAdd(&g_cur[d], 1);
    g_srcs[pos] = s;
    g_dsts[pos] = d;
    float inv = 1.0f / (float)(g_offs[d + 1] - o0);
    ((float4*)g_q)[pos] = edge_q(s, d, inv);
}

// ------------------------------------- standalone nodep (conv1, depends on h)
__global__ void k_nodep(const float* __restrict__ u,
                        const float* __restrict__ c, int K, int n) {
    int warp = (blockIdx.x * blockDim.x + threadIdx.x) >> 5;
    int lane = threadIdx.x & 31;
    nodep_body(warp, lane, g_h, u, c, K, n);
}

// --------------------------------- per-edge q for conv1 (thread per slot)
__global__ void k_edgeq1(int totE) {
    int t = blockIdx.x * blockDim.x + threadIdx.x;
    if (t >= totE) return;
    int s = g_srcs[t], d = g_dsts[t];
    float inv = 1.0f / (float)(g_offs[d + 1] - g_offs[d]);
    ((float4*)g_q)[t] = edge_q(s, d, inv);
}

// ------------------------------------------------ input-space aggregation
// Hot loop: uniform src index + broadcast q + x-row gather + FMA. No softmax.
__device__ __forceinline__ float4 fma4(float4 a, float s, float4 v) {
    a.x += s * v.x; a.y += s * v.y; a.z += s * v.z; a.w += s * v.w; return a;
}
__device__ __forceinline__ void store_split4(uint32_t* dh, uint32_t* dl, float4 r) {
    uint32_t h0, l0, h1, l1;
    split_pair(r.x, r.y, h0, l0);
    split_pair(r.z, r.w, h1, l1);
    *(uint2*)dh = make_uint2(h0, h1);
    *(uint2*)dl = make_uint2(l0, l1);
}

template<int IN, int ZC>
__global__ void k_agg_in(const float* __restrict__ x_ext, int x_sel, int n) {
    constexpr int V = IN / 128;
    int warp = (blockIdx.x * blockDim.x + threadIdx.x) >> 5;
    int lane = threadIdx.x & 31;
    if (warp >= n) return;
    const float* x = x_sel ? g_h : x_ext;
    int i  = warp;
    int s0 = g_offs[i], s1 = g_offs[i + 1];
    if (lane == 0) g_cur[i] = 0;                // deferred reset for next run

    float4 acc[4][V];
    #pragma unroll
    for (int h = 0; h < 4; h++)
        #pragma unroll
        for (int v = 0; v < V; v++) acc[h][v] = make_float4(0.f, 0.f, 0.f, 0.f);

    // 1-deep software pipeline: prefetch next q + x row
    int j = (s0 < s1) ? g_srcs[s0] : 0;
    float4 q = ((const float4*)g_q)[s0 < s1 ? s0 : 0];
    float4 xv[V];
    {
        const float4* xj = (const float4*)(x + (size_t)j * IN);
        #pragma unroll
        for (int v = 0; v < V; v++) xv[v] = (s0 < s1) ? xj[lane + 32 * v]
                                                      : make_float4(0.f,0.f,0.f,0.f);
    }
    for (int e = s0; e < s1; ++e) {
        float4 qn = q;
        float4 xvn[V];
        #pragma unroll
        for (int v = 0; v < V; v++) xvn[v] = xv[v];
        if (e + 1 < s1) {
            int jn = g_srcs[e + 1];
            qn = ((const float4*)g_q)[e + 1];
            const float4* xjn = (const float4*)(x + (size_t)jn * IN);
            #pragma unroll
            for (int v = 0; v < V; v++) xvn[v] = xjn[lane + 32 * v];
        }
        #pragma unroll
        for (int v = 0; v < V; v++) {
            acc[0][v] = fma4(acc[0][v], q.x, xv[v]);
            acc[1][v] = fma4(acc[1][v], q.y, xv[v]);
            acc[2][v] = fma4(acc[2][v], q.z, xv[v]);
            acc[3][v] = fma4(acc[3][v], q.w, xv[v]);
        }
        q = qn;
        #pragma unroll
        for (int v = 0; v < V; v++) xv[v] = xvn[v];
    }
    uint32_t* zh = g_yh + (size_t)i * 512;
    uint32_t* zl = g_yl + (size_t)i * 512;
    #pragma unroll
    for (int h = 0; h < 4; h++)
        #pragma unroll
        for (int v = 0; v < V; v++) {
            int wi = (h * IN) / 2 + 2 * (lane + 32 * v);
            store_split4(zh + wi, zl + wi, acc[h][v]);   // 1/deg folded into q
        }
    if (ZC > 4 * IN) {
        const float4* xi = (const float4*)(x + (size_t)i * IN);
        #pragma unroll
        for (int v = 0; v < V; v++) {
            float4 r = xi[lane + 32 * v];
            int wi = 2 * IN + 2 * (lane + 32 * v);
            store_split4(zh + wi, zl + wi, r);
        }
    }
}

// ----------------------------------------------------- bf16-split MMA GEMM
__device__ __forceinline__ void mma_bf16(float* c, const uint32_t* a, const uint32_t* b) {
    asm volatile(
        "mma.sync.aligned.m16n8k16.row.col.f32.bf16.bf16.f32 "
        "{%0,%1,%2,%3}, {%4,%5,%6,%7}, {%8,%9}, {%0,%1,%2,%3};"
        : "+f"(c[0]), "+f"(c[1]), "+f"(c[2]), "+f"(c[3])
        : "r"(a[0]), "r"(a[1]), "r"(a[2]), "r"(a[3]), "r"(b[0]), "r"(b[1]));
}
__device__ __forceinline__ void cp_async16(uint32_t smem_addr, const void* gptr) {
    asm volatile("cp.async.cg.shared.global [%0], [%1], 16;"
                 :: "r"(smem_addr), "l"(gptr));
}

// C = relu(A@B + b (+b2) (+g_h residual)).  A: g_yh/g_yl. B: g_wb*{0,1}.
// Tile 64(M) x 128(N) x 32(K), 2-stage cp.async pipeline in dynamic smem.
#define AW 20
#define BW 136
#define ST_AH 0
#define ST_AL (64 * AW)
#define ST_BH (2 * 64 * AW)
#define ST_BL (2 * 64 * AW + 16 * BW)
#define STAGE_WORDS (2 * 64 * AW + 2 * 16 * BW)   // 6912 words = 27648 B
#define SMEM_BYTES (2 * STAGE_WORDS * 4)          // 55296 B

__global__ void __launch_bounds__(256, 3) k_mma(const float* __restrict__ b,
                                                const float* __restrict__ b2,
                                                int add_sel, int wsel,
                                                float* __restrict__ out_ext, int out_sel,
                                                int M, int K) {
    extern __shared__ uint32_t dyn[];
    float* C = out_sel ? out_ext : g_h;
    const uint32_t* WH = wsel ? g_wbh1 : g_wbh0;
    const uint32_t* WL = wsel ? g_wbl1 : g_wbl0;

    int tid = threadIdx.x;
    int wid = tid >> 5, lane = tid & 31;
    int g   = lane >> 2;
    int tig = lane & 3;
    int warp_m = (wid >> 2) * 32;
    int warp_n = (wid & 3) * 32;
    int m0 = blockIdx.y * 64;
    int n0 = blockIdx.x * 128;

    float acc[2][4][4];
    #pragma unroll
    for (int i = 0; i < 2; i++)
        #pragma unroll
        for (int j = 0; j < 4; j++)
            #pragma unroll
            for (int q = 0; q < 4; q++) acc[i][j][q] = 0.f;

    int arow = tid >> 2;
    int aseg = (tid & 3) * 4;
    bool a_ok = (m0 + arow) < M;
    int bp = tid >> 5;
    int bn = lane * 4;

    uint32_t base_s = (uint32_t)__cvta_generic_to_shared(dyn);
    uint32_t ah_s[2], al_s[2], bh0_s[2], bh1_s[2], bl0_s[2], bl1_s[2];
    #pragma unroll
    for (int st = 0; st < 2; st++) {
        uint32_t sb = base_s + st * (STAGE_WORDS * 4);
        ah_s[st]  = sb + (ST_AH + arow * AW + aseg) * 4;
        al_s[st]  = sb + (ST_AL + arow * AW + aseg) * 4;
        bh0_s[st] = sb + (ST_BH + bp * BW + bn) * 4;
        bh1_s[st] = sb + (ST_BH + (bp + 8) * BW + bn) * 4;
        bl0_s[st] = sb + (ST_BL + bp * BW + bn) * 4;
        bl1_s[st] = sb + (ST_BL + (bp + 8) * BW + bn) * 4;
    }

    int nsteps = K >> 5;

    auto issue = [&](int st, int step) {
        int k0 = step << 5;
        int gp0 = k0 >> 1;
        cp_async16(bh0_s[st], &WH[(gp0 + bp) * 256 + n0 + bn]);
        cp_async16(bh1_s[st], &WH[(gp0 + bp + 8) * 256 + n0 + bn]);
        cp_async16(bl0_s[st], &WL[(gp0 + bp) * 256 + n0 + bn]);
        cp_async16(bl1_s[st], &WL[(gp0 + bp + 8) * 256 + n0 + bn]);
        if (a_ok) {
            size_t gw = (size_t)(m0 + arow) * 512 + gp0 + aseg;
            cp_async16(ah_s[st], &g_yh[gw]);
            cp_async16(al_s[st], &g_yl[gw]);
        } else {
            uint32_t* st_base = dyn + st * STAGE_WORDS;
            *(uint4*)&st_base[ST_AH + arow * AW + aseg] = make_uint4(0, 0, 0, 0);
            *(uint4*)&st_base[ST_AL + arow * AW + aseg] = make_uint4(0, 0, 0, 0);
        }
        asm volatile("cp.async.commit_group;");
    };

    issue(0, 0);
    for (int s = 0; s < nsteps; s++) {
        int cur = s & 1;
        if (s + 1 < nsteps) {
            issue(cur ^ 1, s + 1);
            asm volatile("cp.async.wait_group 1;");
        } else {
            asm volatile("cp.async.wait_group 0;");
        }
        __syncthreads();

        const uint32_t* Ah = dyn + cur * STAGE_WORDS + ST_AH;
        const uint32_t* Al = dyn + cur * STAGE_WORDS + ST_AL;
        const uint32_t* Bh = dyn + cur * STAGE_WORDS + ST_BH;
        const uint32_t* Bl = dyn + cur * STAGE_WORDS + ST_BL;

        #pragma unroll
        for (int kk2 = 0; kk2 < 2; kk2++) {
            int K0 = kk2 * 8;
            uint32_t ah[2][4], al[2][4];
            #pragma unroll
            for (int mt = 0; mt < 2; mt++) {
                int mr = warp_m + mt * 16 + g;
                ah[mt][0] = Ah[(mr)     * AW + K0 + tig];
                ah[mt][1] = Ah[(mr + 8) * AW + K0 + tig];
                ah[mt][2] = Ah[(mr)     * AW + K0 + 4 + tig];
                ah[mt][3] = Ah[(mr + 8) * AW + K0 + 4 + tig];
                al[mt][0] = Al[(mr)     * AW + K0 + tig];
                al[mt][1] = Al[(mr + 8) * AW + K0 + tig];
                al[mt][2] = Al[(mr)     * AW + K0 + 4 + tig];
                al[mt][3] = Al[(mr + 8) * AW + K0 + 4 + tig];
            }
            #pragma unroll
            for (int nt = 0; nt < 4; nt++) {
                int nc = warp_n + nt * 8 + g;
                uint32_t bh[2], bl[2];
                bh[0] = Bh[(K0 + tig)     * BW + nc];
                bh[1] = Bh[(K0 + 4 + tig) * BW + nc];
                bl[0] = Bl[(K0 + tig)     * BW + nc];
                bl[1] = Bl[(K0 + 4 + tig) * BW + nc];
                #pragma unroll
                for (int mt = 0; mt < 2; mt++) {
                    mma_bf16(acc[mt][nt], ah[mt], bl);
                    mma_bf16(acc[mt][nt], al[mt], bh);
                    mma_bf16(acc[mt][nt], ah[mt], bh);
                }
            }
        }
        __syncthreads();
    }

    // ---- fused epilogue: bias (+bias2) (+residual) + relu ----
    #pragma unroll
    for (int mt = 0; mt < 2; mt++) {
        int r = m0 + warp_m + mt * 16 + g;
        #pragma unroll
        for (int nt = 0; nt < 4; nt++) {
            int cc = n0 + warp_n + nt * 8 + tig * 2;
            float bb0 = b[cc], bb1 = b[cc + 1];
            if (b2) { bb0 += b2[cc]; bb1 += b2[cc + 1]; }
            if (r < M) {
                float v0 = acc[mt][nt][0] + bb0;
                float v1 = acc[mt][nt][1] + bb1;
                if (add_sel) {
                    v0 += g_h[(size_t)r * 256 + cc];
                    v1 += g_h[(size_t)r * 256 + cc + 1];
                }
                C[(size_t)r * 256 + cc]     = fmaxf(v0, 0.f);
                C[(size_t)r * 256 + cc + 1] = fmaxf(v1, 0.f);
            }
            if (r + 8 < M) {
                float v2 = acc[mt][nt][2] + bb0;
                float v3 = acc[mt][nt][3] + bb1;
                if (add_sel) {
                    v2 += g_h[(size_t)(r + 8) * 256 + cc];
                    v3 += g_h[(size_t)(r + 8) * 256 + cc + 1];
                }
                C[(size_t)(r + 8) * 256 + cc]     = fmaxf(v2, 0.f);
                C[(size_t)(r + 8) * 256 + cc + 1] = fmaxf(v3, 0.f);
            }
        }
    }
}

// ---------------------------------------------------------------- launcher
extern "C" void kernel_launch(void* const* d_in, const int* in_sizes, int n_in,
                              void* d_out, int out_size) {
    const float* x      = (const float*)d_in[0];
    const int*   ei     = (const int*)d_in[1];     // int32 (JAX x64 disabled)
    const float* W0     = (const float*)d_in[2];
    const float* u0     = (const float*)d_in[3];
    const float* c0     = (const float*)d_in[4];
    const float* b0     = (const float*)d_in[5];
    const float* skipW0 = (const float*)d_in[6];
    const float* skipb0 = (const float*)d_in[7];
    const float* W1     = (const float*)d_in[8];
    const float* u1     = (const float*)d_in[9];
    const float* c1     = (const float*)d_in[10];
    const float* b1     = (const float*)d_in[11];

    int N = in_sizes[0] / 128;
    int E = in_sizes[1] / 2;
    if (N > MAXN || E > MAXE) return;

    float* out = (float*)d_out;

    cudaFuncSetAttribute(k_mma, cudaFuncAttributeMaxDynamicSharedMemorySize,
                         SMEM_BYTES);

    // phase 0: hist(+edge passthrough) | nodep(conv0) | wsplit -- one launch
    long long hElems = (long long)N * 256;
    int do_edges = ((long long)out_size - hElems >= 2LL * E) ? 1 : 0;
    int HB = (E + 255) / 256;
    int NB = (N * 32 + 255) / 256;
    int WB = ((320 + 512) * 256 + 255) / 256;
    k_phase0<<<HB + NB + WB, 256>>>(ei, out + hElems, E, N, do_edges,
                                    x, u0, c0, W0, skipW0, W1, HB, NB);

    // CSR: scan -> fill (+deg reset, +conv0 edge-q)
    k_scan<<<1, 1024>>>(N);
    k_fill<<<(E + N + 255) / 256, 256>>>(ei, E, N);

    // ---- conv0 ----
    k_agg_in<128, 640><<<(N * 32 + 255) / 256, 256>>>(x, 0, N);
    {   // g_h = relu(z[:,0:640] @ Wstack0 + b0 + skipb0)
        dim3 grid(2, (N + 63) / 64);
        k_mma<<<grid, 256, SMEM_BYTES>>>(b0, skipb0, 0, 0, (float*)nullptr, 0, N, 640);
    }

    // ---- conv1 ----
    k_nodep<<<(N * 32 + 255) / 256, 256>>>(u1, c1, 256, N);
    k_edgeq1<<<(E + N + 255) / 256, 256>>>(E + N);
    k_agg_in<256, 1024><<<(N * 32 + 255) / 256, 256>>>((const float*)nullptr, 1, N);
    {   // out = relu(z @ Wstack1 + b1 + g_h)
        dim3 grid(2, (N + 63) / 64);
        k_mma<<<grid, 256, SMEM_BYTES>>>(b1, (const float*)nullptr, 1, 1, out, 1, N, 1024);
    }
}

// round 16
// speedup vs baseline: 1.0864x; 1.0526x over previous
#include <cuda_runtime.h>
#include <cstdint>

// ---------------------------------------------------------------------------
// FeaStEncoderBlock, input-space aggregation + bf16-split tensor-core GEMM.
// Round 16: copy-free ping-pong edge loop in k_agg_in (unroll-2, two register
// sets, no per-edge MOV chain, no in-loop branch on the A path).
// Everything else as round 15 (319.6us): phase0 mega-kernel, preloaded scan,
// fill+edge-q, GEMM frozen at the legacy-HMMA roofline.
// ---------------------------------------------------------------------------

#define MAXN 20000
#define MAXE 320000

__device__ __align__(16) uint32_t g_yh[(size_t)MAXN * 512];   // z hi pair-words
__device__ __align__(16) uint32_t g_yl[(size_t)MAXN * 512];   // z lo pair-words
__device__ __align__(16) float    g_h[(size_t)MAXN * 256];    // hidden h
__device__ __align__(16) uint32_t g_wbh0[320 * 256];          // conv0 W hi
__device__ __align__(16) uint32_t g_wbl0[320 * 256];          // conv0 W lo
__device__ __align__(16) uint32_t g_wbh1[512 * 256];          // conv1 W hi
__device__ __align__(16) uint32_t g_wbl1[512 * 256];          // conv1 W lo
__device__ __align__(16) float    g_ea[MAXN * 4];
__device__ __align__(16) float    g_eb[MAXN * 4];
__device__ __align__(16) float    g_q[(size_t)(MAXN + MAXE) * 4]; // per-slot q
__device__ int g_deg[MAXN];        // zeroed at load; re-zeroed by k_fill
__device__ int g_cur[MAXN];        // zeroed at load; re-zeroed by k_agg_in
__device__ int g_offs[MAXN + 1];
__device__ int g_srcs[MAXN + MAXE];
__device__ int g_dsts[MAXN + MAXE];

// -------------------------------------------------------- bf16 split utils
__device__ __forceinline__ uint32_t pack_bf16(float lo_elem, float hi_elem) {
    uint32_t r;
    asm("cvt.rn.bf16x2.f32 %0, %1, %2;" : "=r"(r) : "f"(hi_elem), "f"(lo_elem));
    return r;
}
__device__ __forceinline__ void split_pair(float f0, float f1,
                                           uint32_t& hw, uint32_t& lw) {
    hw = pack_bf16(f0, f1);
    float h0 = __uint_as_float(hw << 16);
    float h1 = __uint_as_float(hw & 0xffff0000u);
    lw = pack_bf16(f0 - h0, f1 - h1);
}

// ----------------------------------------------------- per-edge q compute
__device__ __forceinline__ float4 edge_q(int s, int d, float inv) {
    float4 ea = ((const float4*)g_ea)[s];
    float4 eb = ((const float4*)g_eb)[d];
    float q0 = ea.x * eb.x, q1 = ea.y * eb.y, q2 = ea.z * eb.z, q3 = ea.w * eb.w;
    float rz = inv / (q0 + q1 + q2 + q3);
    return make_float4(q0 * rz, q1 * rz, q2 * rz, q3 * rz);
}

// ------------------------------------------ nodep body (shared conv0/conv1)
__device__ __forceinline__ void nodep_body(int warp, int lane,
                                           const float* __restrict__ x,
                                           const float* __restrict__ u,
                                           const float* __restrict__ c,
                                           int K, int n) {
    if (warp >= n) return;
    const float* xr = x + (size_t)warp * K;
    float a0 = 0.f, a1 = 0.f, a2 = 0.f, a3 = 0.f;
    for (int k = lane; k < K; k += 32) {
        float xv = xr[k];
        float4 uv = ((const float4*)u)[k];
        a0 += xv * uv.x; a1 += xv * uv.y; a2 += xv * uv.z; a3 += xv * uv.w;
    }
    #pragma unroll
    for (int off = 16; off; off >>= 1) {
        a0 += __shfl_down_sync(0xffffffffu, a0, off);
        a1 += __shfl_down_sync(0xffffffffu, a1, off);
        a2 += __shfl_down_sync(0xffffffffu, a2, off);
        a3 += __shfl_down_sync(0xffffffffu, a3, off);
    }
    if (lane == 0) {
        float4 ea, eb;
        ea.x = expf(a0 + c[0]); ea.y = expf(a1 + c[1]);
        ea.z = expf(a2 + c[2]); ea.w = expf(a3 + c[3]);
        eb.x = expf(-a0); eb.y = expf(-a1); eb.z = expf(-a2); eb.w = expf(-a3);
        ((float4*)g_ea)[warp] = ea;
        ((float4*)g_eb)[warp] = eb;
    }
}

// ------------------- phase-0 mega-kernel: hist+edges | nodep(conv0) | wsplit
__global__ void k_phase0(const int* __restrict__ ei,
                         float* __restrict__ out_edges,
                         int E, int n, int do_edges,
                         const float* __restrict__ x,
                         const float* __restrict__ u0,
                         const float* __restrict__ c0,
                         const float* __restrict__ W0,
                         const float* __restrict__ skipW0,
                         const float* __restrict__ W1,
                         int HB, int NB) {
    int b = blockIdx.x;
    if (b < HB) {
        int t = b * 256 + threadIdx.x;
        if (t >= E) return;
        int s = ei[t], d = ei[E + t];
        if (do_edges) {
            out_edges[t]     = (float)s;
            out_edges[E + t] = (float)d;
        }
        if (d >= 0 && d < n) atomicAdd(&g_deg[d], 1);
    } else if (b < HB + NB) {
        int warp = ((b - HB) * 256 + threadIdx.x) >> 5;
        int lane = threadIdx.x & 31;
        nodep_body(warp, lane, x, u0, c0, 128, n);
    } else {
        int t = (b - HB - NB) * 256 + threadIdx.x;
        if (t < 320 * 256) {
            int p = t >> 8, d = t & 255;
            float f[2];
            #pragma unroll
            for (int e = 0; e < 2; e++) {
                int r = 2 * p + e;
                if (r < 512) { int h = r >> 7, c = r & 127; f[e] = W0[c * 1024 + h * 256 + d]; }
                else         { int c = r - 512;             f[e] = skipW0[c * 256 + d]; }
            }
            uint32_t hw, lw;
            split_pair(f[0], f[1], hw, lw);
            g_wbh0[t] = hw; g_wbl0[t] = lw;
        }
        int t1 = t - 320 * 256;
        if (t1 >= 0 && t1 < 512 * 256) {
            int p = t1 >> 8, d = t1 & 255;
            float f[2];
            #pragma unroll
            for (int e = 0; e < 2; e++) {
                int r = 2 * p + e;
                int h = r >> 8, c = r & 255;
                f[e] = W1[c * 1024 + h * 256 + d];
            }
            uint32_t hw, lw;
            split_pair(f[0], f[1], hw, lw);
            g_wbh1[t1] = hw; g_wbl1[t1] = lw;
        }
    }
}

// single-block exclusive scan; 10 preloaded values/thread (self-loop +1 folded)
__global__ void k_scan(int n) {
    __shared__ int wsum[32];
    __shared__ int carry;
    const int VPT = 10;
    const int CH  = 1024 * VPT;
    int tid = threadIdx.x, lane = tid & 31, w = tid >> 5;
    if (tid == 0) carry = 0;
    __syncthreads();
    int nch = (n + CH - 1) / CH;
    for (int ch = 0; ch < nch; ++ch) {
        int i0 = ch * CH + tid * VPT;
        int p[VPT];
        int run = 0;
        #pragma unroll
        for (int k = 0; k < VPT; k++) {
            int idx = i0 + k;
            int v = (idx < n) ? (g_deg[idx] + 1) : 0;   // +1 = self loop
            run += v;
            p[k] = run;
        }
        int s = run;
        #pragma unroll
        for (int o = 1; o < 32; o <<= 1) {
            int t2 = __shfl_up_sync(0xffffffffu, s, o);
            if (lane >= o) s += t2;
        }
        if (lane == 31) wsum[w] = s;
        __syncthreads();
        if (w == 0) {
            int ws = wsum[lane];
            #pragma unroll
            for (int o = 1; o < 32; o <<= 1) {
                int t2 = __shfl_up_sync(0xffffffffu, ws, o);
                if (lane >= o) ws += t2;
            }
            wsum[lane] = ws;
        }
        __syncthreads();
        int base = carry + (w ? wsum[w - 1] : 0) + (s - run);
        #pragma unroll
        for (int k = 0; k < VPT; k++) {
            int idx = i0 + k;
            if (idx < n) g_offs[idx + 1] = base + p[k];
        }
        __syncthreads();
        if (tid == 1023) carry = base + run;
        __syncthreads();
    }
    if (threadIdx.x == 0) g_offs[0] = 0;
}

// fill CSR + compute conv0 per-edge q (ea/eb ready from phase0)
__global__ void k_fill(const int* __restrict__ ei, int E, int n) {
    int t = blockIdx.x * blockDim.x + threadIdx.x;
    if (t < n) g_deg[t] = 0;                    // deferred reset for next run
    if (t >= E + n) return;
    int s, d;
    if (t < E) { s = ei[t]; d = ei[E + t]; }
    else       { s = d = t - E; }               // self loop
    if (s < 0 || s >= n || d < 0 || d >= n) return;
    int o0 = g_offs[d];
    int pos = o0 + atomicAdd(&g_cur[d], 1);
    g_srcs[pos] = s;
    g_dsts[pos] = d;
    float inv = 1.0f / (float)(g_offs[d + 1] - o0);
    ((float4*)g_q)[pos] = edge_q(s, d, inv);
}

// ------------------------------------- standalone nodep (conv1, depends on h)
__global__ void k_nodep(const float* __restrict__ u,
                        const float* __restrict__ c, int K, int n) {
    int warp = (blockIdx.x * blockDim.x + threadIdx.x) >> 5;
    int lane = threadIdx.x & 31;
    nodep_body(warp, lane, g_h, u, c, K, n);
}

// --------------------------------- per-edge q for conv1 (thread per slot)
__global__ void k_edgeq1(int totE) {
    int t = blockIdx.x * blockDim.x + threadIdx.x;
    if (t >= totE) return;
    int s = g_srcs[t], d = g_dsts[t];
    float inv = 1.0f / (float)(g_offs[d + 1] - g_offs[d]);
    ((float4*)g_q)[t] = edge_q(s, d, inv);
}

// ------------------------------------------------ input-space aggregation
// Ping-pong unroll-2 edge loop: no register copies, no in-loop A-branch.
__device__ __forceinline__ float4 fma4(float4 a, float s, float4 v) {
    a.x += s * v.x; a.y += s * v.y; a.z += s * v.z; a.w += s * v.w; return a;
}
__device__ __forceinline__ void store_split4(uint32_t* dh, uint32_t* dl, float4 r) {
    uint32_t h0, l0, h1, l1;
    split_pair(r.x, r.y, h0, l0);
    split_pair(r.z, r.w, h1, l1);
    *(uint2*)dh = make_uint2(h0, h1);
    *(uint2*)dl = make_uint2(l0, l1);
}

template<int IN, int ZC>
__global__ void __launch_bounds__(256) k_agg_in(const float* __restrict__ x_ext,
                                                int x_sel, int n) {
    constexpr int V = IN / 128;
    int warp = (blockIdx.x * blockDim.x + threadIdx.x) >> 5;
    int lane = threadIdx.x & 31;
    if (warp >= n) return;
    const float* x = x_sel ? g_h : x_ext;
    int i  = warp;
    int s0 = g_offs[i], s1 = g_offs[i + 1];
    if (lane == 0) g_cur[i] = 0;                // deferred reset for next run

    float4 acc[4][V];
    #pragma unroll
    for (int h = 0; h < 4; h++)
        #pragma unroll
        for (int v = 0; v < V; v++) acc[h][v] = make_float4(0.f, 0.f, 0.f, 0.f);

    // two independent prefetch register sets (deg >= 1 guaranteed: self loop)
    float4 qA, qB;
    float4 xA[V], xB[V];

    // load slot e into the given set
    #define LOAD_SET(qr, xr, slot) do {                                        \
        int _j = g_srcs[(slot)];                                               \
        qr = ((const float4*)g_q)[(slot)];                                     \
        const float4* _xj = (const float4*)(x + (size_t)_j * IN);              \
        _Pragma("unroll")                                                      \
        for (int _v = 0; _v < V; _v++) xr[_v] = _xj[lane + 32 * _v];           \
    } while (0)

    #define FMA_SET(qr, xr) do {                                               \
        _Pragma("unroll")                                                      \
        for (int _v = 0; _v < V; _v++) {                                       \
            acc[0][_v] = fma4(acc[0][_v], qr.x, xr[_v]);                       \
            acc[1][_v] = fma4(acc[1][_v], qr.y, xr[_v]);                       \
            acc[2][_v] = fma4(acc[2][_v], qr.z, xr[_v]);                       \
            acc[3][_v] = fma4(acc[3][_v], qr.w, xr[_v]);                       \
        }                                                                      \
    } while (0)

    int e = s0;
    LOAD_SET(qA, xA, e);
    if (s1 - s0 > 1) LOAD_SET(qB, xB, e + 1);

    for (; e + 2 < s1; e += 2) {
        FMA_SET(qA, xA);
        LOAD_SET(qA, xA, e + 2);                 // unconditional: e+2 < s1
        FMA_SET(qB, xB);
        if (e + 3 < s1) LOAD_SET(qB, xB, e + 3);
    }
    // remainder: s1 - e is 1 or 2
    FMA_SET(qA, xA);
    if (s1 - e == 2) FMA_SET(qB, xB);

    #undef LOAD_SET
    #undef FMA_SET

    uint32_t* zh = g_yh + (size_t)i * 512;
    uint32_t* zl = g_yl + (size_t)i * 512;
    #pragma unroll
    for (int h = 0; h < 4; h++)
        #pragma unroll
        for (int v = 0; v < V; v++) {
            int wi = (h * IN) / 2 + 2 * (lane + 32 * v);
            store_split4(zh + wi, zl + wi, acc[h][v]);   // 1/deg folded into q
        }
    if (ZC > 4 * IN) {
        const float4* xi = (const float4*)(x + (size_t)i * IN);
        #pragma unroll
        for (int v = 0; v < V; v++) {
            float4 r = xi[lane + 32 * v];
            int wi = 2 * IN + 2 * (lane + 32 * v);
            store_split4(zh + wi, zl + wi, r);
        }
    }
}

// ----------------------------------------------------- bf16-split MMA GEMM
__device__ __forceinline__ void mma_bf16(float* c, const uint32_t* a, const uint32_t* b) {
    asm volatile(
        "mma.sync.aligned.m16n8k16.row.col.f32.bf16.bf16.f32 "
        "{%0,%1,%2,%3}, {%4,%5,%6,%7}, {%8,%9}, {%0,%1,%2,%3};"
        : "+f"(c[0]), "+f"(c[1]), "+f"(c[2]), "+f"(c[3])
        : "r"(a[0]), "r"(a[1]), "r"(a[2]), "r"(a[3]), "r"(b[0]), "r"(b[1]));
}
__device__ __forceinline__ void cp_async16(uint32_t smem_addr, const void* gptr) {
    asm volatile("cp.async.cg.shared.global [%0], [%1], 16;"
                 :: "r"(smem_addr), "l"(gptr));
}

// C = relu(A@B + b (+b2) (+g_h residual)).  A: g_yh/g_yl. B: g_wb*{0,1}.
// Tile 64(M) x 128(N) x 32(K), 2-stage cp.async pipeline in dynamic smem.
#define AW 20
#define BW 136
#define ST_AH 0
#define ST_AL (64 * AW)
#define ST_BH (2 * 64 * AW)
#define ST_BL (2 * 64 * AW + 16 * BW)
#define STAGE_WORDS (2 * 64 * AW + 2 * 16 * BW)   // 6912 words = 27648 B
#define SMEM_BYTES (2 * STAGE_WORDS * 4)          // 55296 B

__global__ void __launch_bounds__(256, 3) k_mma(const float* __restrict__ b,
                                                const float* __restrict__ b2,
                                                int add_sel, int wsel,
                                                float* __restrict__ out_ext, int out_sel,
                                                int M, int K) {
    extern __shared__ uint32_t dyn[];
    float* C = out_sel ? out_ext : g_h;
    const uint32_t* WH = wsel ? g_wbh1 : g_wbh0;
    const uint32_t* WL = wsel ? g_wbl1 : g_wbl0;

    int tid = threadIdx.x;
    int wid = tid >> 5, lane = tid & 31;
    int g   = lane >> 2;
    int tig = lane & 3;
    int warp_m = (wid >> 2) * 32;
    int warp_n = (wid & 3) * 32;
    int m0 = blockIdx.y * 64;
    int n0 = blockIdx.x * 128;

    float acc[2][4][4];
    #pragma unroll
    for (int i = 0; i < 2; i++)
        #pragma unroll
        for (int j = 0; j < 4; j++)
            #pragma unroll
            for (int q = 0; q < 4; q++) acc[i][j][q] = 0.f;

    int arow = tid >> 2;
    int aseg = (tid & 3) * 4;
    bool a_ok = (m0 + arow) < M;
    int bp = tid >> 5;
    int bn = lane * 4;

    uint32_t base_s = (uint32_t)__cvta_generic_to_shared(dyn);
    uint32_t ah_s[2], al_s[2], bh0_s[2], bh1_s[2], bl0_s[2], bl1_s[2];
    #pragma unroll
    for (int st = 0; st < 2; st++) {
        uint32_t sb = base_s + st * (STAGE_WORDS * 4);
        ah_s[st]  = sb + (ST_AH + arow * AW + aseg) * 4;
        al_s[st]  = sb + (ST_AL + arow * AW + aseg) * 4;
        bh0_s[st] = sb + (ST_BH + bp * BW + bn) * 4;
        bh1_s[st] = sb + (ST_BH + (bp + 8) * BW + bn) * 4;
        bl0_s[st] = sb + (ST_BL + bp * BW + bn) * 4;
        bl1_s[st] = sb + (ST_BL + (bp + 8) * BW + bn) * 4;
    }

    int nsteps = K >> 5;

    auto issue = [&](int st, int step) {
        int k0 = step << 5;
        int gp0 = k0 >> 1;
        cp_async16(bh0_s[st], &WH[(gp0 + bp) * 256 + n0 + bn]);
        cp_async16(bh1_s[st], &WH[(gp0 + bp + 8) * 256 + n0 + bn]);
        cp_async16(bl0_s[st], &WL[(gp0 + bp) * 256 + n0 + bn]);
        cp_async16(bl1_s[st], &WL[(gp0 + bp + 8) * 256 + n0 + bn]);
        if (a_ok) {
            size_t gw = (size_t)(m0 + arow) * 512 + gp0 + aseg;
            cp_async16(ah_s[st], &g_yh[gw]);
            cp_async16(al_s[st], &g_yl[gw]);
        } else {
            uint32_t* st_base = dyn + st * STAGE_WORDS;
            *(uint4*)&st_base[ST_AH + arow * AW + aseg] = make_uint4(0, 0, 0, 0);
            *(uint4*)&st_base[ST_AL + arow * AW + aseg] = make_uint4(0, 0, 0, 0);
        }
        asm volatile("cp.async.commit_group;");
    };

    issue(0, 0);
    for (int s = 0; s < nsteps; s++) {
        int cur = s & 1;
        if (s + 1 < nsteps) {
            issue(cur ^ 1, s + 1);
            asm volatile("cp.async.wait_group 1;");
        } else {
            asm volatile("cp.async.wait_group 0;");
        }
        __syncthreads();

        const uint32_t* Ah = dyn + cur * STAGE_WORDS + ST_AH;
        const uint32_t* Al = dyn + cur * STAGE_WORDS + ST_AL;
        const uint32_t* Bh = dyn + cur * STAGE_WORDS + ST_BH;
        const uint32_t* Bl = dyn + cur * STAGE_WORDS + ST_BL;

        #pragma unroll
        for (int kk2 = 0; kk2 < 2; kk2++) {
            int K0 = kk2 * 8;
            uint32_t ah[2][4], al[2][4];
            #pragma unroll
            for (int mt = 0; mt < 2; mt++) {
                int mr = warp_m + mt * 16 + g;
                ah[mt][0] = Ah[(mr)     * AW + K0 + tig];
                ah[mt][1] = Ah[(mr + 8) * AW + K0 + tig];
                ah[mt][2] = Ah[(mr)     * AW + K0 + 4 + tig];
                ah[mt][3] = Ah[(mr + 8) * AW + K0 + 4 + tig];
                al[mt][0] = Al[(mr)     * AW + K0 + tig];
                al[mt][1] = Al[(mr + 8) * AW + K0 + tig];
                al[mt][2] = Al[(mr)     * AW + K0 + 4 + tig];
                al[mt][3] = Al[(mr + 8) * AW + K0 + 4 + tig];
            }
            #pragma unroll
            for (int nt = 0; nt < 4; nt++) {
                int nc = warp_n + nt * 8 + g;
                uint32_t bh[2], bl[2];
                bh[0] = Bh[(K0 + tig)     * BW + nc];
                bh[1] = Bh[(K0 + 4 + tig) * BW + nc];
                bl[0] = Bl[(K0 + tig)     * BW + nc];
                bl[1] = Bl[(K0 + 4 + tig) * BW + nc];
                #pragma unroll
                for (int mt = 0; mt < 2; mt++) {
                    mma_bf16(acc[mt][nt], ah[mt], bl);
                    mma_bf16(acc[mt][nt], al[mt], bh);
                    mma_bf16(acc[mt][nt], ah[mt], bh);
                }
            }
        }
        __syncthreads();
    }

    // ---- fused epilogue: bias (+bias2) (+residual) + relu ----
    #pragma unroll
    for (int mt = 0; mt < 2; mt++) {
        int r = m0 + warp_m + mt * 16 + g;
        #pragma unroll
        for (int nt = 0; nt < 4; nt++) {
            int cc = n0 + warp_n + nt * 8 + tig * 2;
            float bb0 = b[cc], bb1 = b[cc + 1];
            if (b2) { bb0 += b2[cc]; bb1 += b2[cc + 1]; }
            if (r < M) {
                float v0 = acc[mt][nt][0] + bb0;
                float v1 = acc[mt][nt][1] + bb1;
                if (add_sel) {
                    v0 += g_h[(size_t)r * 256 + cc];
                    v1 += g_h[(size_t)r * 256 + cc + 1];
                }
                C[(size_t)r * 256 + cc]     = fmaxf(v0, 0.f);
                C[(size_t)r * 256 + cc + 1] = fmaxf(v1, 0.f);
            }
            if (r + 8 < M) {
                float v2 = acc[mt][nt][2] + bb0;
                float v3 = acc[mt][nt][3] + bb1;
                if (add_sel) {
                    v2 += g_h[(size_t)(r + 8) * 256 + cc];
                    v3 += g_h[(size_t)(r + 8) * 256 + cc + 1];
                }
                C[(size_t)(r + 8) * 256 + cc]     = fmaxf(v2, 0.f);
                C[(size_t)(r + 8) * 256 + cc + 1] = fmaxf(v3, 0.f);
            }
        }
    }
}

// ---------------------------------------------------------------- launcher
extern "C" void kernel_launch(void* const* d_in, const int* in_sizes, int n_in,
                              void* d_out, int out_size) {
    const float* x      = (const float*)d_in[0];
    const int*   ei     = (const int*)d_in[1];     // int32 (JAX x64 disabled)
    const float* W0     = (const float*)d_in[2];
    const float* u0     = (const float*)d_in[3];
    const float* c0     = (const float*)d_in[4];
    const float* b0     = (const float*)d_in[5];
    const float* skipW0 = (const float*)d_in[6];
    const float* skipb0 = (const float*)d_in[7];
    const float* W1     = (const float*)d_in[8];
    const float* u1     = (const float*)d_in[9];
    const float* c1     = (const float*)d_in[10];
    const float* b1     = (const float*)d_in[11];

    int N = in_sizes[0] / 128;
    int E = in_sizes[1] / 2;
    if (N > MAXN || E > MAXE) return;

    float* out = (float*)d_out;

    cudaFuncSetAttribute(k_mma, cudaFuncAttributeMaxDynamicSharedMemorySize,
                         SMEM_BYTES);

    // phase 0: hist(+edge passthrough) | nodep(conv0) | wsplit -- one launch
    long long hElems = (long long)N * 256;
    int do_edges = ((long long)out_size - hElems >= 2LL * E) ? 1 : 0;
    int HB = (E + 255) / 256;
    int NB = (N * 32 + 255) / 256;
    int WB = ((320 + 512) * 256 + 255) / 256;
    k_phase0<<<HB + NB + WB, 256>>>(ei, out + hElems, E, N, do_edges,
                                    x, u0, c0, W0, skipW0, W1, HB, NB);

    // CSR: scan -> fill (+deg reset, +conv0 edge-q)
    k_scan<<<1, 1024>>>(N);
    k_fill<<<(E + N + 255) / 256, 256>>>(ei, E, N);

    // ---- conv0 ----
    k_agg_in<128, 640><<<(N * 32 + 255) / 256, 256>>>(x, 0, N);
    {   // g_h = relu(z[:,0:640] @ Wstack0 + b0 + skipb0)
        dim3 grid(2, (N + 63) / 64);
        k_mma<<<grid, 256, SMEM_BYTES>>>(b0, skipb0, 0, 0, (float*)nullptr, 0, N, 640);
    }

    // ---- conv1 ----
    k_nodep<<<(N * 32 + 255) / 256, 256>>>(u1, c1, 256, N);
    k_edgeq1<<<(E + N + 255) / 256, 256>>>(E + N);
    k_agg_in<256, 1024><<<(N * 32 + 255) / 256, 256>>>((const float*)nullptr, 1, N);
    {   // out = relu(z @ Wstack1 + b1 + g_h)
        dim3 grid(2, (N + 63) / 64);
        k_mma<<<grid, 256, SMEM_BYTES>>>(b1, (const float*)nullptr, 1, 1, out, 1, N, 1024);
    }
}

// round 17
// speedup vs baseline: 1.0872x; 1.0007x over previous
#include <cuda_runtime.h>
#include <cstdint>

// ---------------------------------------------------------------------------
// FeaStEncoderBlock, input-space aggregation + bf16-split tensor-core GEMM.
// Round 17: conv1 aggregation split 2-warps-per-node (V=1 per warp, lower
// register pressure, 2x warps for latency hiding). conv0 agg unchanged.
// GEMM frozen: measured 273 TF/s == legacy-HMMA hw roofline (rt=16cyc/SMSP).
// ---------------------------------------------------------------------------

#define MAXN 20000
#define MAXE 320000

__device__ __align__(16) uint32_t g_yh[(size_t)MAXN * 512];   // z hi pair-words
__device__ __align__(16) uint32_t g_yl[(size_t)MAXN * 512];   // z lo pair-words
__device__ __align__(16) float    g_h[(size_t)MAXN * 256];    // hidden h
__device__ __align__(16) uint32_t g_wbh0[320 * 256];          // conv0 W hi
__device__ __align__(16) uint32_t g_wbl0[320 * 256];          // conv0 W lo
__device__ __align__(16) uint32_t g_wbh1[512 * 256];          // conv1 W hi
__device__ __align__(16) uint32_t g_wbl1[512 * 256];          // conv1 W lo
__device__ __align__(16) float    g_ea[MAXN * 4];
__device__ __align__(16) float    g_eb[MAXN * 4];
__device__ __align__(16) float    g_q[(size_t)(MAXN + MAXE) * 4]; // per-slot q
__device__ int g_deg[MAXN];        // zeroed at load; re-zeroed by k_fill
__device__ int g_cur[MAXN];        // zeroed at load; re-zeroed by k_agg_in
__device__ int g_offs[MAXN + 1];
__device__ int g_srcs[MAXN + MAXE];
__device__ int g_dsts[MAXN + MAXE];

// -------------------------------------------------------- bf16 split utils
__device__ __forceinline__ uint32_t pack_bf16(float lo_elem, float hi_elem) {
    uint32_t r;
    asm("cvt.rn.bf16x2.f32 %0, %1, %2;" : "=r"(r) : "f"(hi_elem), "f"(lo_elem));
    return r;
}
__device__ __forceinline__ void split_pair(float f0, float f1,
                                           uint32_t& hw, uint32_t& lw) {
    hw = pack_bf16(f0, f1);
    float h0 = __uint_as_float(hw << 16);
    float h1 = __uint_as_float(hw & 0xffff0000u);
    lw = pack_bf16(f0 - h0, f1 - h1);
}

// ----------------------------------------------------- per-edge q compute
__device__ __forceinline__ float4 edge_q(int s, int d, float inv) {
    float4 ea = ((const float4*)g_ea)[s];
    float4 eb = ((const float4*)g_eb)[d];
    float q0 = ea.x * eb.x, q1 = ea.y * eb.y, q2 = ea.z * eb.z, q3 = ea.w * eb.w;
    float rz = inv / (q0 + q1 + q2 + q3);
    return make_float4(q0 * rz, q1 * rz, q2 * rz, q3 * rz);
}

// ------------------------------------------ nodep body (shared conv0/conv1)
__device__ __forceinline__ void nodep_body(int warp, int lane,
                                           const float* __restrict__ x,
                                           const float* __restrict__ u,
                                           const float* __restrict__ c,
                                           int K, int n) {
    if (warp >= n) return;
    const float* xr = x + (size_t)warp * K;
    float a0 = 0.f, a1 = 0.f, a2 = 0.f, a3 = 0.f;
    for (int k = lane; k < K; k += 32) {
        float xv = xr[k];
        float4 uv = ((const float4*)u)[k];
        a0 += xv * uv.x; a1 += xv * uv.y; a2 += xv * uv.z; a3 += xv * uv.w;
    }
    #pragma unroll
    for (int off = 16; off; off >>= 1) {
        a0 += __shfl_down_sync(0xffffffffu, a0, off);
        a1 += __shfl_down_sync(0xffffffffu, a1, off);
        a2 += __shfl_down_sync(0xffffffffu, a2, off);
        a3 += __shfl_down_sync(0xffffffffu, a3, off);
    }
    if (lane == 0) {
        float4 ea, eb;
        ea.x = expf(a0 + c[0]); ea.y = expf(a1 + c[1]);
        ea.z = expf(a2 + c[2]); ea.w = expf(a3 + c[3]);
        eb.x = expf(-a0); eb.y = expf(-a1); eb.z = expf(-a2); eb.w = expf(-a3);
        ((float4*)g_ea)[warp] = ea;
        ((float4*)g_eb)[warp] = eb;
    }
}

// ------------------- phase-0 mega-kernel: hist+edges | nodep(conv0) | wsplit
__global__ void k_phase0(const int* __restrict__ ei,
                         float* __restrict__ out_edges,
                         int E, int n, int do_edges,
                         const float* __restrict__ x,
                         const float* __restrict__ u0,
                         const float* __restrict__ c0,
                         const float* __restrict__ W0,
                         const float* __restrict__ skipW0,
                         const float* __restrict__ W1,
                         int HB, int NB) {
    int b = blockIdx.x;
    if (b < HB) {
        int t = b * 256 + threadIdx.x;
        if (t >= E) return;
        int s = ei[t], d = ei[E + t];
        if (do_edges) {
            out_edges[t]     = (float)s;
            out_edges[E + t] = (float)d;
        }
        if (d >= 0 && d < n) atomicAdd(&g_deg[d], 1);
    } else if (b < HB + NB) {
        int warp = ((b - HB) * 256 + threadIdx.x) >> 5;
        int lane = threadIdx.x & 31;
        nodep_body(warp, lane, x, u0, c0, 128, n);
    } else {
        int t = (b - HB - NB) * 256 + threadIdx.x;
        if (t < 320 * 256) {
            int p = t >> 8, d = t & 255;
            float f[2];
            #pragma unroll
            for (int e = 0; e < 2; e++) {
                int r = 2 * p + e;
                if (r < 512) { int h = r >> 7, c = r & 127; f[e] = W0[c * 1024 + h * 256 + d]; }
                else         { int c = r - 512;             f[e] = skipW0[c * 256 + d]; }
            }
            uint32_t hw, lw;
            split_pair(f[0], f[1], hw, lw);
            g_wbh0[t] = hw; g_wbl0[t] = lw;
        }
        int t1 = t - 320 * 256;
        if (t1 >= 0 && t1 < 512 * 256) {
            int p = t1 >> 8, d = t1 & 255;
            float f[2];
            #pragma unroll
            for (int e = 0; e < 2; e++) {
                int r = 2 * p + e;
                int h = r >> 8, c = r & 255;
                f[e] = W1[c * 1024 + h * 256 + d];
            }
            uint32_t hw, lw;
            split_pair(f[0], f[1], hw, lw);
            g_wbh1[t1] = hw; g_wbl1[t1] = lw;
        }
    }
}

// single-block exclusive scan; 10 preloaded values/thread (self-loop +1 folded)
__global__ void k_scan(int n) {
    __shared__ int wsum[32];
    __shared__ int carry;
    const int VPT = 10;
    const int CH  = 1024 * VPT;
    int tid = threadIdx.x, lane = tid & 31, w = tid >> 5;
    if (tid == 0) carry = 0;
    __syncthreads();
    int nch = (n + CH - 1) / CH;
    for (int ch = 0; ch < nch; ++ch) {
        int i0 = ch * CH + tid * VPT;
        int p[VPT];
        int run = 0;
        #pragma unroll
        for (int k = 0; k < VPT; k++) {
            int idx = i0 + k;
            int v = (idx < n) ? (g_deg[idx] + 1) : 0;   // +1 = self loop
            run += v;
            p[k] = run;
        }
        int s = run;
        #pragma unroll
        for (int o = 1; o < 32; o <<= 1) {
            int t2 = __shfl_up_sync(0xffffffffu, s, o);
            if (lane >= o) s += t2;
        }
        if (lane == 31) wsum[w] = s;
        __syncthreads();
        if (w == 0) {
            int ws = wsum[lane];
            #pragma unroll
            for (int o = 1; o < 32; o <<= 1) {
                int t2 = __shfl_up_sync(0xffffffffu, ws, o);
                if (lane >= o) ws += t2;
            }
            wsum[lane] = ws;
        }
        __syncthreads();
        int base = carry + (w ? wsum[w - 1] : 0) + (s - run);
        #pragma unroll
        for (int k = 0; k < VPT; k++) {
            int idx = i0 + k;
            if (idx < n) g_offs[idx + 1] = base + p[k];
        }
        __syncthreads();
        if (tid == 1023) carry = base + run;
        __syncthreads();
    }
    if (threadIdx.x == 0) g_offs[0] = 0;
}

// fill CSR + compute conv0 per-edge q (ea/eb ready from phase0)
__global__ void k_fill(const int* __restrict__ ei, int E, int n) {
    int t = blockIdx.x * blockDim.x + threadIdx.x;
    if (t < n) g_deg[t] = 0;                    // deferred reset for next run
    if (t >= E + n) return;
    int s, d;
    if (t < E) { s = ei[t]; d = ei[E + t]; }
    else       { s = d = t - E; }               // self loop
    if (s < 0 || s >= n || d < 0 || d >= n) return;
    int o0 = g_offs[d];
    int pos = o0 + atomicAdd(&g_cur[d], 1);
    g_srcs[pos] = s;
    g_dsts[pos] = d;
    float inv = 1.0f / (float)(g_offs[d + 1] - o0);
    ((float4*)g_q)[pos] = edge_q(s, d, inv);
}

// ------------------------------------- standalone nodep (conv1, depends on h)
__global__ void k_nodep(const float* __restrict__ u,
                        const float* __restrict__ c, int K, int n) {
    int warp = (blockIdx.x * blockDim.x + threadIdx.x) >> 5;
    int lane = threadIdx.x & 31;
    nodep_body(warp, lane, g_h, u, c, K, n);
}

// --------------------------------- per-edge q for conv1 (thread per slot)
__global__ void k_edgeq1(int totE) {
    int t = blockIdx.x * blockDim.x + threadIdx.x;
    if (t >= totE) return;
    int s = g_srcs[t], d = g_dsts[t];
    float inv = 1.0f / (float)(g_offs[d + 1] - g_offs[d]);
    ((float4*)g_q)[t] = edge_q(s, d, inv);
}

// ------------------------------------------------ input-space aggregation
// Ping-pong unroll-2 edge loop. WPN warps cooperate per node, each owning
// 128 channels (V=1 float4 per lane per set).
__device__ __forceinline__ float4 fma4(float4 a, float s, float4 v) {
    a.x += s * v.x; a.y += s * v.y; a.z += s * v.z; a.w += s * v.w; return a;
}
__device__ __forceinline__ void store_split4(uint32_t* dh, uint32_t* dl, float4 r) {
    uint32_t h0, l0, h1, l1;
    split_pair(r.x, r.y, h0, l0);
    split_pair(r.z, r.w, h1, l1);
    *(uint2*)dh = make_uint2(h0, h1);
    *(uint2*)dl = make_uint2(l0, l1);
}

template<int IN, int ZC, int WPN>
__global__ void __launch_bounds__(256) k_agg_in(const float* __restrict__ x_ext,
                                                int x_sel, int n) {
    int gwarp = (blockIdx.x * blockDim.x + threadIdx.x) >> 5;
    int lane = threadIdx.x & 31;
    int i    = gwarp / WPN;            // node
    int half = gwarp % WPN;            // channel-half owned by this warp
    if (i >= n) return;
    const float* x = x_sel ? g_h : x_ext;
    int s0 = g_offs[i], s1 = g_offs[i + 1];
    if (half == 0 && lane == 0) g_cur[i] = 0;   // deferred reset for next run

    // this warp's float4 column within the x row (32 float4 = 128 floats)
    int coff = half * 32 + lane;

    float4 acc[4];
    #pragma unroll
    for (int h = 0; h < 4; h++) acc[h] = make_float4(0.f, 0.f, 0.f, 0.f);

    float4 qA, qB;
    float4 xA, xB;

    #define LOAD_SET(qr, xr, slot) do {                                        \
        int _j = g_srcs[(slot)];                                               \
        qr = ((const float4*)g_q)[(slot)];                                     \
        xr = ((const float4*)(x + (size_t)_j * IN))[coff];                     \
    } while (0)

    #define FMA_SET(qr, xr) do {                                               \
        acc[0] = fma4(acc[0], qr.x, xr);                                       \
        acc[1] = fma4(acc[1], qr.y, xr);                                       \
        acc[2] = fma4(acc[2], qr.z, xr);                                       \
        acc[3] = fma4(acc[3], qr.w, xr);                                       \
    } while (0)

    int e = s0;
    LOAD_SET(qA, xA, e);
    if (s1 - s0 > 1) LOAD_SET(qB, xB, e + 1);

    for (; e + 2 < s1; e += 2) {
        FMA_SET(qA, xA);
        LOAD_SET(qA, xA, e + 2);                 // unconditional: e+2 < s1
        FMA_SET(qB, xB);
        if (e + 3 < s1) LOAD_SET(qB, xB, e + 3);
    }
    FMA_SET(qA, xA);
    if (s1 - e == 2) FMA_SET(qB, xB);

    #undef LOAD_SET
    #undef FMA_SET

    uint32_t* zh = g_yh + (size_t)i * 512;
    uint32_t* zl = g_yl + (size_t)i * 512;
    #pragma unroll
    for (int h = 0; h < 4; h++) {
        int wi = h * (IN / 2) + half * 64 + 2 * lane;
        store_split4(zh + wi, zl + wi, acc[h]);      // 1/deg folded into q
    }
    if (ZC > 4 * IN) {                               // skip-concat tail (conv0)
        float4 r = ((const float4*)(x + (size_t)i * IN))[coff];
        int wi = 2 * IN + half * 64 + 2 * lane;
        store_split4(zh + wi, zl + wi, r);
    }
}

// ----------------------------------------------------- bf16-split MMA GEMM
__device__ __forceinline__ void mma_bf16(float* c, const uint32_t* a, const uint32_t* b) {
    asm volatile(
        "mma.sync.aligned.m16n8k16.row.col.f32.bf16.bf16.f32 "
        "{%0,%1,%2,%3}, {%4,%5,%6,%7}, {%8,%9}, {%0,%1,%2,%3};"
        : "+f"(c[0]), "+f"(c[1]), "+f"(c[2]), "+f"(c[3])
        : "r"(a[0]), "r"(a[1]), "r"(a[2]), "r"(a[3]), "r"(b[0]), "r"(b[1]));
}
__device__ __forceinline__ void cp_async16(uint32_t smem_addr, const void* gptr) {
    asm volatile("cp.async.cg.shared.global [%0], [%1], 16;"
                 :: "r"(smem_addr), "l"(gptr));
}

// C = relu(A@B + b (+b2) (+g_h residual)).  A: g_yh/g_yl. B: g_wb*{0,1}.
// Tile 64(M) x 128(N) x 32(K), 2-stage cp.async pipeline in dynamic smem.
#define AW 20
#define BW 136
#define ST_AH 0
#define ST_AL (64 * AW)
#define ST_BH (2 * 64 * AW)
#define ST_BL (2 * 64 * AW + 16 * BW)
#define STAGE_WORDS (2 * 64 * AW + 2 * 16 * BW)   // 6912 words = 27648 B
#define SMEM_BYTES (2 * STAGE_WORDS * 4)          // 55296 B

__global__ void __launch_bounds__(256, 3) k_mma(const float* __restrict__ b,
                                                const float* __restrict__ b2,
                                                int add_sel, int wsel,
                                                float* __restrict__ out_ext, int out_sel,
                                                int M, int K) {
    extern __shared__ uint32_t dyn[];
    float* C = out_sel ? out_ext : g_h;
    const uint32_t* WH = wsel ? g_wbh1 : g_wbh0;
    const uint32_t* WL = wsel ? g_wbl1 : g_wbl0;

    int tid = threadIdx.x;
    int wid = tid >> 5, lane = tid & 31;
    int g   = lane >> 2;
    int tig = lane & 3;
    int warp_m = (wid >> 2) * 32;
    int warp_n = (wid & 3) * 32;
    int m0 = blockIdx.y * 64;
    int n0 = blockIdx.x * 128;

    float acc[2][4][4];
    #pragma unroll
    for (int i = 0; i < 2; i++)
        #pragma unroll
        for (int j = 0; j < 4; j++)
            #pragma unroll
            for (int q = 0; q < 4; q++) acc[i][j][q] = 0.f;

    int arow = tid >> 2;
    int aseg = (tid & 3) * 4;
    bool a_ok = (m0 + arow) < M;
    int bp = tid >> 5;
    int bn = lane * 4;

    uint32_t base_s = (uint32_t)__cvta_generic_to_shared(dyn);
    uint32_t ah_s[2], al_s[2], bh0_s[2], bh1_s[2], bl0_s[2], bl1_s[2];
    #pragma unroll
    for (int st = 0; st < 2; st++) {
        uint32_t sb = base_s + st * (STAGE_WORDS * 4);
        ah_s[st]  = sb + (ST_AH + arow * AW + aseg) * 4;
        al_s[st]  = sb + (ST_AL + arow * AW + aseg) * 4;
        bh0_s[st] = sb + (ST_BH + bp * BW + bn) * 4;
        bh1_s[st] = sb + (ST_BH + (bp + 8) * BW + bn) * 4;
        bl0_s[st] = sb + (ST_BL + bp * BW + bn) * 4;
        bl1_s[st] = sb + (ST_BL + (bp + 8) * BW + bn) * 4;
    }

    int nsteps = K >> 5;

    auto issue = [&](int st, int step) {
        int k0 = step << 5;
        int gp0 = k0 >> 1;
        cp_async16(bh0_s[st], &WH[(gp0 + bp) * 256 + n0 + bn]);
        cp_async16(bh1_s[st], &WH[(gp0 + bp + 8) * 256 + n0 + bn]);
        cp_async16(bl0_s[st], &WL[(gp0 + bp) * 256 + n0 + bn]);
        cp_async16(bl1_s[st], &WL[(gp0 + bp + 8) * 256 + n0 + bn]);
        if (a_ok) {
            size_t gw = (size_t)(m0 + arow) * 512 + gp0 + aseg;
            cp_async16(ah_s[st], &g_yh[gw]);
            cp_async16(al_s[st], &g_yl[gw]);
        } else {
            uint32_t* st_base = dyn + st * STAGE_WORDS;
            *(uint4*)&st_base[ST_AH + arow * AW + aseg] = make_uint4(0, 0, 0, 0);
            *(uint4*)&st_base[ST_AL + arow * AW + aseg] = make_uint4(0, 0, 0, 0);
        }
        asm volatile("cp.async.commit_group;");
    };

    issue(0, 0);
    for (int s = 0; s < nsteps; s++) {
        int cur = s & 1;
        if (s + 1 < nsteps) {
            issue(cur ^ 1, s + 1);
            asm volatile("cp.async.wait_group 1;");
        } else {
            asm volatile("cp.async.wait_group 0;");
        }
        __syncthreads();

        const uint32_t* Ah = dyn + cur * STAGE_WORDS + ST_AH;
        const uint32_t* Al = dyn + cur * STAGE_WORDS + ST_AL;
        const uint32_t* Bh = dyn + cur * STAGE_WORDS + ST_BH;
        const uint32_t* Bl = dyn + cur * STAGE_WORDS + ST_BL;

        #pragma unroll
        for (int kk2 = 0; kk2 < 2; kk2++) {
            int K0 = kk2 * 8;
            uint32_t ah[2][4], al[2][4];
            #pragma unroll
            for (int mt = 0; mt < 2; mt++) {
                int mr = warp_m + mt * 16 + g;
                ah[mt][0] = Ah[(mr)     * AW + K0 + tig];
                ah[mt][1] = Ah[(mr + 8) * AW + K0 + tig];
                ah[mt][2] = Ah[(mr)     * AW + K0 + 4 + tig];
                ah[mt][3] = Ah[(mr + 8) * AW + K0 + 4 + tig];
                al[mt][0] = Al[(mr)     * AW + K0 + tig];
                al[mt][1] = Al[(mr + 8) * AW + K0 + tig];
                al[mt][2] = Al[(mr)     * AW + K0 + 4 + tig];
                al[mt][3] = Al[(mr + 8) * AW + K0 + 4 + tig];
            }
            #pragma unroll
            for (int nt = 0; nt < 4; nt++) {
                int nc = warp_n + nt * 8 + g;
                uint32_t bh[2], bl[2];
                bh[0] = Bh[(K0 + tig)     * BW + nc];
                bh[1] = Bh[(K0 + 4 + tig) * BW + nc];
                bl[0] = Bl[(K0 + tig)     * BW + nc];
                bl[1] = Bl[(K0 + 4 + tig) * BW + nc];
                #pragma unroll
                for (int mt = 0; mt < 2; mt++) {
                    mma_bf16(acc[mt][nt], ah[mt], bl);
                    mma_bf16(acc[mt][nt], al[mt], bh);
                    mma_bf16(acc[mt][nt], ah[mt], bh);
                }
            }
        }
        __syncthreads();
    }

    // ---- fused epilogue: bias (+bias2) (+residual) + relu ----
    #pragma unroll
    for (int mt = 0; mt < 2; mt++) {
        int r = m0 + warp_m + mt * 16 + g;
        #pragma unroll
        for (int nt = 0; nt < 4; nt++) {
            int cc = n0 + warp_n + nt * 8 + tig * 2;
            float bb0 = b[cc], bb1 = b[cc + 1];
            if (b2) { bb0 += b2[cc]; bb1 += b2[cc + 1]; }
            if (r < M) {
                float v0 = acc[mt][nt][0] + bb0;
                float v1 = acc[mt][nt][1] + bb1;
                if (add_sel) {
                    v0 += g_h[(size_t)r * 256 + cc];
                    v1 += g_h[(size_t)r * 256 + cc + 1];
                }
                C[(size_t)r * 256 + cc]     = fmaxf(v0, 0.f);
                C[(size_t)r * 256 + cc + 1] = fmaxf(v1, 0.f);
            }
            if (r + 8 < M) {
                float v2 = acc[mt][nt][2] + bb0;
                float v3 = acc[mt][nt][3] + bb1;
                if (add_sel) {
                    v2 += g_h[(size_t)(r + 8) * 256 + cc];
                    v3 += g_h[(size_t)(r + 8) * 256 + cc + 1];
                }
                C[(size_t)(r + 8) * 256 + cc]     = fmaxf(v2, 0.f);
                C[(size_t)(r + 8) * 256 + cc + 1] = fmaxf(v3, 0.f);
            }
        }
    }
}

// ---------------------------------------------------------------- launcher
extern "C" void kernel_launch(void* const* d_in, const int* in_sizes, int n_in,
                              void* d_out, int out_size) {
    const float* x      = (const float*)d_in[0];
    const int*   ei     = (const int*)d_in[1];     // int32 (JAX x64 disabled)
    const float* W0     = (const float*)d_in[2];
    const float* u0     = (const float*)d_in[3];
    const float* c0     = (const float*)d_in[4];
    const float* b0     = (const float*)d_in[5];
    const float* skipW0 = (const float*)d_in[6];
    const float* skipb0 = (const float*)d_in[7];
    const float* W1     = (const float*)d_in[8];
    const float* u1     = (const float*)d_in[9];
    const float* c1     = (const float*)d_in[10];
    const float* b1     = (const float*)d_in[11];

    int N = in_sizes[0] / 128;
    int E = in_sizes[1] / 2;
    if (N > MAXN || E > MAXE) return;

    float* out = (float*)d_out;

    cudaFuncSetAttribute(k_mma, cudaFuncAttributeMaxDynamicSharedMemorySize,
                         SMEM_BYTES);

    // phase 0: hist(+edge passthrough) | nodep(conv0) | wsplit -- one launch
    long long hElems = (long long)N * 256;
    int do_edges = ((long long)out_size - hElems >= 2LL * E) ? 1 : 0;
    int HB = (E + 255) / 256;
    int NB = (N * 32 + 255) / 256;
    int WB = ((320 + 512) * 256 + 255) / 256;
    k_phase0<<<HB + NB + WB, 256>>>(ei, out + hElems, E, N, do_edges,
                                    x, u0, c0, W0, skipW0, W1, HB, NB);

    // CSR: scan -> fill (+deg reset, +conv0 edge-q)
    k_scan<<<1, 1024>>>(N);
    k_fill<<<(E + N + 255) / 256, 256>>>(ei, E, N);

    // ---- conv0 ----
    k_agg_in<128, 640, 1><<<(N * 32 + 255) / 256, 256>>>(x, 0, N);
    {   // g_h = relu(z[:,0:640] @ Wstack0 + b0 + skipb0)
        dim3 grid(2, (N + 63) / 64);
        k_mma<<<grid, 256, SMEM_BYTES>>>(b0, skipb0, 0, 0, (float*)nullptr, 0, N, 640);
    }

    // ---- conv1 ----
    k_nodep<<<(N * 32 + 255) / 256, 256>>>(u1, c1, 256, N);
    k_edgeq1<<<(E + N + 255) / 256, 256>>>(E + N);
    k_agg_in<256, 1024, 2><<<(N * 64 + 255) / 256, 256>>>((const float*)nullptr, 1, N);
    {   // out = relu(z @ Wstack1 + b1 + g_h)
        dim3 grid(2, (N + 63) / 64);
        k_mma<<<grid, 256, SMEM_BYTES>>>(b1, (const float*)nullptr, 1, 1, out, 1, N, 1024);
    }
}